// round 1
// baseline (speedup 1.0000x reference)
#include <cuda_runtime.h>
#include <math.h>
#include <stdint.h>

// Problem constants
#define BB   4
#define SS   2048
#define DD   768
#define HH   12
#define DHH  64
#define DFF  3072
#define MR   8192          // B*S
#define EPSL 1e-5f

// ---------------- scratch (allocation-free: one big __device__ array) -------
// layout: q,k,v,ctx,x1,h  (each 8192*768) then ff (8192*3072)
#define SZ_D   (MR * DD)          // 6291456
#define SZ_FF  (MR * DFF)         // 25165824
static __device__ float g_scratch[6 * SZ_D + SZ_FF];

#define OFF_Q    0
#define OFF_K    (1 * SZ_D)
#define OFF_V    (2 * SZ_D)
#define OFF_CTX  (3 * SZ_D)
#define OFF_X1   (4 * SZ_D)
#define OFF_H    (5 * SZ_D)
#define OFF_FF   (6 * SZ_D)

// ---------------- helpers ----------------------------------------------------
__device__ __forceinline__ float gelu_exact(float x) {
    return 0.5f * x * (1.0f + erff(x * 0.70710678118654752f));
}

// ---------------- generic SGEMM: C = A[MxK] * B[KxN] + bias (+epi) ----------
// EPI: 0 = bias, 1 = bias + residual, 2 = bias + gelu
// Requires M%128==0, N%128==0, K%8==0.
template <int EPI>
__global__ __launch_bounds__(256) void sgemm128(
    const float* __restrict__ A, const float* __restrict__ Bm,
    const float* __restrict__ bias, const float* __restrict__ res,
    float* __restrict__ C, int M, int N, int K)
{
    __shared__ float As[2][8][128];   // transposed: As[k][m]
    __shared__ float Bs[2][8][128];   // Bs[k][n]

    const int tid = threadIdx.x;
    const int bm = blockIdx.y * 128;
    const int bn = blockIdx.x * 128;

    const int arow = tid >> 1;            // 0..127
    const int acol = (tid & 1) * 4;       // 0 or 4
    const int brow = tid >> 5;            // 0..7
    const int bcol = (tid & 31) * 4;      // 0..124

    const int tx = tid & 15;
    const int ty = tid >> 4;

    float acc[8][8];
#pragma unroll
    for (int i = 0; i < 8; ++i)
#pragma unroll
        for (int j = 0; j < 8; ++j) acc[i][j] = 0.0f;

    const float* Aptr = A + (size_t)(bm + arow) * K + acol;
    const float* Bptr = Bm + (size_t)brow * N + bn + bcol;

    // preload tile 0
    float4 pa = *(const float4*)(Aptr);
    float4 pb = *(const float4*)(Bptr);
    As[0][acol + 0][arow] = pa.x;
    As[0][acol + 1][arow] = pa.y;
    As[0][acol + 2][arow] = pa.z;
    As[0][acol + 3][arow] = pa.w;
    *(float4*)&Bs[0][brow][bcol] = pb;
    __syncthreads();

    const int ntile = K >> 3;
    for (int t = 0; t < ntile; ++t) {
        const int cur = t & 1;
        if (t + 1 < ntile) {
            pa = *(const float4*)(Aptr + (t + 1) * 8);
            pb = *(const float4*)(Bptr + (size_t)(t + 1) * 8 * N);
        }
#pragma unroll
        for (int kk = 0; kk < 8; ++kk) {
            float4 a0 = *(const float4*)&As[cur][kk][ty * 4];
            float4 a1 = *(const float4*)&As[cur][kk][64 + ty * 4];
            float4 b0 = *(const float4*)&Bs[cur][kk][tx * 4];
            float4 b1 = *(const float4*)&Bs[cur][kk][64 + tx * 4];
            float av[8] = {a0.x, a0.y, a0.z, a0.w, a1.x, a1.y, a1.z, a1.w};
            float bv[8] = {b0.x, b0.y, b0.z, b0.w, b1.x, b1.y, b1.z, b1.w};
#pragma unroll
            for (int i = 0; i < 8; ++i)
#pragma unroll
                for (int j = 0; j < 8; ++j)
                    acc[i][j] = fmaf(av[i], bv[j], acc[i][j]);
        }
        if (t + 1 < ntile) {
            const int nxt = cur ^ 1;
            As[nxt][acol + 0][arow] = pa.x;
            As[nxt][acol + 1][arow] = pa.y;
            As[nxt][acol + 2][arow] = pa.z;
            As[nxt][acol + 3][arow] = pa.w;
            *(float4*)&Bs[nxt][brow][bcol] = pb;
        }
        __syncthreads();
    }

    // epilogue
#pragma unroll
    for (int hi = 0; hi < 2; ++hi) {
#pragma unroll
        for (int i = 0; i < 4; ++i) {
            const int row = bm + hi * 64 + ty * 4 + i;
#pragma unroll
            for (int hj = 0; hj < 2; ++hj) {
                const int col = bn + hj * 64 + tx * 4;
                const float4 bb = *(const float4*)&bias[col];
                float4 r4;
                r4.x = acc[hi * 4 + i][hj * 4 + 0] + bb.x;
                r4.y = acc[hi * 4 + i][hj * 4 + 1] + bb.y;
                r4.z = acc[hi * 4 + i][hj * 4 + 2] + bb.z;
                r4.w = acc[hi * 4 + i][hj * 4 + 3] + bb.w;
                if (EPI == 1) {
                    const float4 rr = *(const float4*)&res[(size_t)row * N + col];
                    r4.x += rr.x; r4.y += rr.y; r4.z += rr.z; r4.w += rr.w;
                }
                if (EPI == 2) {
                    r4.x = gelu_exact(r4.x);
                    r4.y = gelu_exact(r4.y);
                    r4.z = gelu_exact(r4.z);
                    r4.w = gelu_exact(r4.w);
                }
                *(float4*)&C[(size_t)row * N + col] = r4;
            }
        }
    }
}

// ---------------- flash attention: per (b,h, 64-row q tile) -----------------
// q/k/v in [B*S, D] layout (head h occupies cols h*64..h*64+63)
__global__ __launch_bounds__(256) void attn_kernel(
    const float* __restrict__ q, const float* __restrict__ k,
    const float* __restrict__ v, float* __restrict__ ctx)
{
    extern __shared__ float sm[];
    float* Qs = sm;               // [64][68]   d-major: Qs[d][r]
    float* Ks = Qs + 64 * 68;     // [64][68]   d-major: Ks[d][c]
    float* Vs = Ks + 64 * 68;     // [64][68]   natural: Vs[c][dh]
    float* Ps = Vs + 64 * 68;     // [64][68]   transposed: Ps[c][r]

    const int bh = blockIdx.x;            // 0..47
    const int qt = blockIdx.y;            // 0..31
    const int b = bh / HH;
    const int h = bh % HH;
    const int tid = threadIdx.x;
    const int tx = tid & 15;
    const int ty = tid >> 4;
    const int q0 = qt * 64;

    const size_t base = (size_t)(b * SS) * DD + h * 64;

    // load Q tile (transposed store)
#pragma unroll
    for (int rep = 0; rep < 4; ++rep) {
        const int idx = tid + rep * 256;       // float4 index 0..1023
        const int r = idx >> 4;
        const int d4 = (idx & 15) << 2;
        const float4 t4 = *(const float4*)(q + base + (size_t)(q0 + r) * DD + d4);
        Qs[(d4 + 0) * 68 + r] = t4.x;
        Qs[(d4 + 1) * 68 + r] = t4.y;
        Qs[(d4 + 2) * 68 + r] = t4.z;
        Qs[(d4 + 3) * 68 + r] = t4.w;
    }

    float m_i[4], l_i[4], acc[4][4];
#pragma unroll
    for (int i = 0; i < 4; ++i) {
        m_i[i] = -INFINITY;
        l_i[i] = 0.0f;
#pragma unroll
        for (int j = 0; j < 4; ++j) acc[i][j] = 0.0f;
    }
    __syncthreads();

    for (int kt = 0; kt < SS / 64; ++kt) {
        // load K (transposed) + V (natural)
#pragma unroll
        for (int rep = 0; rep < 4; ++rep) {
            const int idx = tid + rep * 256;
            const int r = idx >> 4;
            const int d4 = (idx & 15) << 2;
            const size_t goff = base + (size_t)(kt * 64 + r) * DD + d4;
            const float4 kk = *(const float4*)(k + goff);
            Ks[(d4 + 0) * 68 + r] = kk.x;
            Ks[(d4 + 1) * 68 + r] = kk.y;
            Ks[(d4 + 2) * 68 + r] = kk.z;
            Ks[(d4 + 3) * 68 + r] = kk.w;
            const float4 vv = *(const float4*)(v + goff);
            *(float4*)&Vs[r * 68 + d4] = vv;
        }
        __syncthreads();

        // scores S[r][c] = sum_d Q[r][d]*K[c][d]
        float s[4][4];
#pragma unroll
        for (int i = 0; i < 4; ++i)
#pragma unroll
            for (int j = 0; j < 4; ++j) s[i][j] = 0.0f;

#pragma unroll
        for (int d = 0; d < 64; ++d) {
            const float4 a = *(const float4*)&Qs[d * 68 + ty * 4];
            const float4 bb = *(const float4*)&Ks[d * 68 + tx * 4];
            const float av[4] = {a.x, a.y, a.z, a.w};
            const float bv[4] = {bb.x, bb.y, bb.z, bb.w};
#pragma unroll
            for (int i = 0; i < 4; ++i)
#pragma unroll
                for (int j = 0; j < 4; ++j)
                    s[i][j] = fmaf(av[i], bv[j], s[i][j]);
        }

        // online softmax (rows owned across the 16 tx lanes)
#pragma unroll
        for (int i = 0; i < 4; ++i) {
            float mx = -INFINITY;
#pragma unroll
            for (int j = 0; j < 4; ++j) {
                s[i][j] *= 0.125f;   // 1/sqrt(64)
                mx = fmaxf(mx, s[i][j]);
            }
#pragma unroll
            for (int off = 8; off >= 1; off >>= 1)
                mx = fmaxf(mx, __shfl_xor_sync(0xffffffffu, mx, off, 16));

            const float mnew = fmaxf(m_i[i], mx);
            const float corr = __expf(m_i[i] - mnew);
            float rsum = 0.0f;
#pragma unroll
            for (int j = 0; j < 4; ++j) {
                const float p = __expf(s[i][j] - mnew);
                s[i][j] = p;
                rsum += p;
            }
#pragma unroll
            for (int off = 8; off >= 1; off >>= 1)
                rsum += __shfl_xor_sync(0xffffffffu, rsum, off, 16);

            l_i[i] = l_i[i] * corr + rsum;
#pragma unroll
            for (int j = 0; j < 4; ++j) acc[i][j] *= corr;
            m_i[i] = mnew;
        }

        // write P transposed: Ps[c][r]
#pragma unroll
        for (int j = 0; j < 4; ++j) {
            float4 pj;
            pj.x = s[0][j]; pj.y = s[1][j]; pj.z = s[2][j]; pj.w = s[3][j];
            *(float4*)&Ps[(tx * 4 + j) * 68 + ty * 4] = pj;
        }
        __syncthreads();

        // acc[r][dh] += sum_c P[r][c]*V[c][dh]
#pragma unroll
        for (int c = 0; c < 64; ++c) {
            const float4 a = *(const float4*)&Ps[c * 68 + ty * 4];
            const float4 bb = *(const float4*)&Vs[c * 68 + tx * 4];
            const float av[4] = {a.x, a.y, a.z, a.w};
            const float bv[4] = {bb.x, bb.y, bb.z, bb.w};
#pragma unroll
            for (int i = 0; i < 4; ++i)
#pragma unroll
                for (int j = 0; j < 4; ++j)
                    acc[i][j] = fmaf(av[i], bv[j], acc[i][j]);
        }
        __syncthreads();
    }

    // write ctx
#pragma unroll
    for (int i = 0; i < 4; ++i) {
        const float inv = 1.0f / l_i[i];
        float4 o;
        o.x = acc[i][0] * inv; o.y = acc[i][1] * inv;
        o.z = acc[i][2] * inv; o.w = acc[i][3] * inv;
        *(float4*)(ctx + base + (size_t)(q0 + ty * 4 + i) * DD + tx * 4) = o;
    }
}

// ---------------- layernorm: one block per row -------------------------------
__global__ __launch_bounds__(256) void ln_kernel(
    const float* __restrict__ x, const float* __restrict__ g,
    const float* __restrict__ bta, float* __restrict__ y)
{
    const int row = blockIdx.x;
    const float* xr = x + (size_t)row * DD;
    const int tid = threadIdx.x;
    const int lane = tid & 31;
    const int wid = tid >> 5;

    float vals[3];
#pragma unroll
    for (int i = 0; i < 3; ++i) vals[i] = xr[tid + i * 256];

    __shared__ float red[32];

    float sum = vals[0] + vals[1] + vals[2];
#pragma unroll
    for (int off = 16; off >= 1; off >>= 1)
        sum += __shfl_xor_sync(0xffffffffu, sum, off);
    if (lane == 0) red[wid] = sum;
    __syncthreads();
    if (tid < 32) {
        float t = (lane < 8) ? red[lane] : 0.0f;
#pragma unroll
        for (int off = 4; off >= 1; off >>= 1)
            t += __shfl_xor_sync(0xffffffffu, t, off);
        if (lane == 0) red[0] = t * (1.0f / DD);
    }
    __syncthreads();
    const float mu = red[0];
    __syncthreads();

    float vs = 0.0f;
#pragma unroll
    for (int i = 0; i < 3; ++i) {
        const float d = vals[i] - mu;
        vs += d * d;
    }
#pragma unroll
    for (int off = 16; off >= 1; off >>= 1)
        vs += __shfl_xor_sync(0xffffffffu, vs, off);
    if (lane == 0) red[wid] = vs;
    __syncthreads();
    if (tid < 32) {
        float t = (lane < 8) ? red[lane] : 0.0f;
#pragma unroll
        for (int off = 4; off >= 1; off >>= 1)
            t += __shfl_xor_sync(0xffffffffu, t, off);
        if (lane == 0) red[0] = t * (1.0f / DD);
    }
    __syncthreads();
    const float rstd = rsqrtf(red[0] + EPSL);

    float* yr = y + (size_t)row * DD;
#pragma unroll
    for (int i = 0; i < 3; ++i) {
        const int c = tid + i * 256;
        yr[c] = (vals[i] - mu) * rstd * g[c] + bta[c];
    }
}

// ---------------- launch ------------------------------------------------------
extern "C" void kernel_launch(void* const* d_in, const int* in_sizes, int n_in,
                              void* d_out, int out_size)
{
    (void)in_sizes; (void)n_in; (void)out_size;
    const float* Q    = (const float*)d_in[0];
    const float* K    = (const float*)d_in[1];
    const float* V    = (const float*)d_in[2];
    const float* Wq   = (const float*)d_in[3];
    const float* bq   = (const float*)d_in[4];
    const float* Wk   = (const float*)d_in[5];
    const float* bk   = (const float*)d_in[6];
    const float* Wv   = (const float*)d_in[7];
    const float* bv   = (const float*)d_in[8];
    const float* Wo   = (const float*)d_in[9];
    const float* bo   = (const float*)d_in[10];
    const float* ln_g = (const float*)d_in[11];
    const float* ln_b = (const float*)d_in[12];
    const float* W1   = (const float*)d_in[13];
    const float* b1   = (const float*)d_in[14];
    const float* W2   = (const float*)d_in[15];
    const float* b2   = (const float*)d_in[16];
    float* out = (float*)d_out;

    float* scr = nullptr;
    cudaGetSymbolAddress((void**)&scr, g_scratch);
    float* gq   = scr + OFF_Q;
    float* gk   = scr + OFF_K;
    float* gv   = scr + OFF_V;
    float* gctx = scr + OFF_CTX;
    float* gx1  = scr + OFF_X1;
    float* gh   = scr + OFF_H;
    float* gff  = scr + OFF_FF;

    const size_t attn_smem = 4 * 64 * 68 * sizeof(float);   // 69632 B
    cudaFuncSetAttribute(attn_kernel,
                         cudaFuncAttributeMaxDynamicSharedMemorySize,
                         (int)attn_smem);

    const dim3 blk(256);
    const dim3 g768(DD / 128, MR / 128);     // (6, 64)
    const dim3 g3072(DFF / 128, MR / 128);   // (24, 64)

    // QKV projections
    sgemm128<0><<<g768, blk>>>(Q, Wq, bq, nullptr, gq, MR, DD, DD);
    sgemm128<0><<<g768, blk>>>(K, Wk, bk, nullptr, gk, MR, DD, DD);
    sgemm128<0><<<g768, blk>>>(V, Wv, bv, nullptr, gv, MR, DD, DD);

    // attention
    const dim3 gattn(BB * HH, SS / 64);      // (48, 32)
    attn_kernel<<<gattn, blk, attn_smem>>>(gq, gk, gv, gctx);

    // output projection + residual
    sgemm128<1><<<g768, blk>>>(gctx, Wo, bo, Q, gx1, MR, DD, DD);

    // layernorm
    ln_kernel<<<MR, blk>>>(gx1, ln_g, ln_b, gh);

    // FFN
    sgemm128<2><<<g3072, blk>>>(gh, W1, b1, nullptr, gff, MR, DFF, DD);
    sgemm128<0><<<g768, blk>>>(gff, W2, b2, nullptr, out, MR, DD, DFF);
}

// round 3
// speedup vs baseline: 1.6576x; 1.6576x over previous
#include <cuda_runtime.h>
#include <math.h>
#include <stdint.h>

// Problem constants
#define BB   4
#define SS   2048
#define DD   768
#define HH   12
#define DFF  3072
#define MR   8192          // B*S
#define EPSL 1e-5f

// ---------------- scratch ----------------------------------------------------
#define SZ_D   (MR * DD)
#define SZ_FF  (MR * DFF)
static __device__ float g_scratch[6 * SZ_D + SZ_FF];

#define OFF_Q    0
#define OFF_K    (1 * SZ_D)
#define OFF_V    (2 * SZ_D)
#define OFF_CTX  (3 * SZ_D)
#define OFF_X1   (4 * SZ_D)
#define OFF_H    (5 * SZ_D)
#define OFF_FF   (6 * SZ_D)

// ---------------- helpers ----------------------------------------------------
__device__ __forceinline__ float gelu_exact(float x) {
    return 0.5f * x * (1.0f + erff(x * 0.70710678118654752f));
}

__device__ __forceinline__ uint32_t tf32r(float x) {
    uint32_t u;
    asm("cvt.rna.tf32.f32 %0, %1;" : "=r"(u) : "f"(x));
    return u;
}

__device__ __forceinline__ void cpa16(uint32_t s, const void* g) {
    asm volatile("cp.async.cg.shared.global [%0], [%1], 16;" :: "r"(s), "l"(g));
}

__device__ __forceinline__ uint32_t smem_u32(const void* p) {
    uint32_t a;
    asm("{ .reg .u64 t; cvta.to.shared.u64 t, %1; cvt.u32.u64 %0, t; }"
        : "=r"(a) : "l"(p));
    return a;
}

// tf32 warp MMA: D(16x8) += A(16x8) * B(8x8)
__device__ __forceinline__ void mma8(float* c, const uint32_t* a, const uint32_t* b) {
    asm volatile(
        "mma.sync.aligned.m16n8k8.row.col.f32.tf32.tf32.f32 "
        "{%0,%1,%2,%3}, {%4,%5,%6,%7}, {%8,%9}, {%0,%1,%2,%3};"
        : "+f"(c[0]), "+f"(c[1]), "+f"(c[2]), "+f"(c[3])
        : "r"(a[0]), "r"(a[1]), "r"(a[2]), "r"(a[3]), "r"(b[0]), "r"(b[1]));
}

// ---------------- tf32 mma.sync GEMM -----------------------------------------
// C[M,N] = A[M,K] @ B[K,N] + bias (+epi). M%128==0, N%128==0, K%16==0.
// EPI: 0 bias, 1 bias+residual, 2 bias+gelu
#define APAD 20
#define BPAD 136

template <int EPI>
__global__ __launch_bounds__(256) void mma_gemm(
    const float* __restrict__ A, const float* __restrict__ Bm,
    const float* __restrict__ bias, const float* __restrict__ res,
    float* __restrict__ C, int M, int N, int K)
{
    __shared__ float As[2][128][APAD];   // rows m, 16 k-cols used (pad 20)
    __shared__ float Bs[2][16][BPAD];    // rows k, 128 n-cols used (pad 136)

    const int tid = threadIdx.x;
    const int wid = tid >> 5;
    const int lane = tid & 31;
    const int wm = wid & 1;          // 2 warps in M
    const int wn = wid >> 1;         // 4 warps in N
    const int row4 = lane >> 2;      // 0..7
    const int kc = lane & 3;         // 0..3

    const int bm = blockIdx.y << 7;
    const int bn = blockIdx.x << 7;

    float acc[4][4][4];
#pragma unroll
    for (int i = 0; i < 4; ++i)
#pragma unroll
        for (int j = 0; j < 4; ++j)
#pragma unroll
            for (int q = 0; q < 4; ++q) acc[i][j][q] = 0.0f;

    const uint32_t sA = smem_u32(&As[0][0][0]);
    const uint32_t sB = smem_u32(&Bs[0][0][0]);
    const uint32_t stA = 128u * APAD * 4u;   // bytes per A stage
    const uint32_t stB = 16u * BPAD * 4u;    // bytes per B stage

    const int KT = K >> 4;

    auto load_stage = [&](int kt) {
        const int buf = kt & 1;
        const int k0 = kt << 4;
#pragma unroll
        for (int i = 0; i < 2; ++i) {
            const int c = tid + i * 256;          // 0..511
            // A chunk: m = c>>2, kq = c&3
            {
                const int m = c >> 2, kq = c & 3;
                cpa16(sA + buf * stA + (uint32_t)(m * APAD + kq * 4) * 4u,
                      A + (size_t)(bm + m) * K + k0 + kq * 4);
            }
            // B chunk: k = c>>5, nq = c&31
            {
                const int k = c >> 5, nq = c & 31;
                cpa16(sB + buf * stB + (uint32_t)(k * BPAD + nq * 4) * 4u,
                      Bm + (size_t)(k0 + k) * N + bn + nq * 4);
            }
        }
        asm volatile("cp.async.commit_group;" ::: "memory");
    };

    load_stage(0);

    for (int kt = 0; kt < KT; ++kt) {
        const int cur = kt & 1;
        if (kt + 1 < KT) {
            load_stage(kt + 1);
            asm volatile("cp.async.wait_group 1;" ::: "memory");
        } else {
            asm volatile("cp.async.wait_group 0;" ::: "memory");
        }
        __syncthreads();

#pragma unroll
        for (int kk = 0; kk < 2; ++kk) {
            const int kb = kk * 8;
            uint32_t au[4][4], bu[4][2];
#pragma unroll
            for (int mt = 0; mt < 4; ++mt) {
                const int m = wm * 64 + mt * 16 + row4;
                au[mt][0] = tf32r(As[cur][m][kb + kc]);
                au[mt][1] = tf32r(As[cur][m + 8][kb + kc]);
                au[mt][2] = tf32r(As[cur][m][kb + kc + 4]);
                au[mt][3] = tf32r(As[cur][m + 8][kb + kc + 4]);
            }
#pragma unroll
            for (int nt = 0; nt < 4; ++nt) {
                const int n = wn * 32 + nt * 8 + row4;
                bu[nt][0] = tf32r(Bs[cur][kb + kc][n]);
                bu[nt][1] = tf32r(Bs[cur][kb + kc + 4][n]);
            }
#pragma unroll
            for (int mt = 0; mt < 4; ++mt)
#pragma unroll
                for (int nt = 0; nt < 4; ++nt)
                    mma8(acc[mt][nt], au[mt], bu[nt]);
        }
        __syncthreads();
    }

    // epilogue: c0,c1 at (row, col..col+1); c2,c3 at (row+8, ...)
#pragma unroll
    for (int mt = 0; mt < 4; ++mt) {
        const int r0 = bm + wm * 64 + mt * 16 + row4;
#pragma unroll
        for (int nt = 0; nt < 4; ++nt) {
            const int col = bn + wn * 32 + nt * 8 + kc * 2;
            const float b0 = bias[col], b1 = bias[col + 1];
            float v0 = acc[mt][nt][0] + b0;
            float v1 = acc[mt][nt][1] + b1;
            float v2 = acc[mt][nt][2] + b0;
            float v3 = acc[mt][nt][3] + b1;
            if (EPI == 1) {
                const float2 ra = *(const float2*)&res[(size_t)r0 * N + col];
                const float2 rb = *(const float2*)&res[(size_t)(r0 + 8) * N + col];
                v0 += ra.x; v1 += ra.y; v2 += rb.x; v3 += rb.y;
            }
            if (EPI == 2) {
                v0 = gelu_exact(v0); v1 = gelu_exact(v1);
                v2 = gelu_exact(v2); v3 = gelu_exact(v3);
            }
            *(float2*)&C[(size_t)r0 * N + col] = make_float2(v0, v1);
            *(float2*)&C[(size_t)(r0 + 8) * N + col] = make_float2(v2, v3);
        }
    }
}

// ---------------- flash attention (fp32, as round 1) -------------------------
__global__ __launch_bounds__(256) void attn_kernel(
    const float* __restrict__ q, const float* __restrict__ k,
    const float* __restrict__ v, float* __restrict__ ctx)
{
    extern __shared__ float sm[];
    float* Qs = sm;               // [64][68]   d-major
    float* Ks = Qs + 64 * 68;     // [64][68]   d-major
    float* Vs = Ks + 64 * 68;     // [64][68]   natural
    float* Ps = Vs + 64 * 68;     // [64][68]   transposed

    const int bh = blockIdx.x;
    const int qt = blockIdx.y;
    const int b = bh / HH;
    const int h = bh % HH;
    const int tid = threadIdx.x;
    const int tx = tid & 15;
    const int ty = tid >> 4;
    const int q0 = qt * 64;

    const size_t base = (size_t)(b * SS) * DD + h * 64;

#pragma unroll
    for (int rep = 0; rep < 4; ++rep) {
        const int idx = tid + rep * 256;
        const int r = idx >> 4;
        const int d4 = (idx & 15) << 2;
        const float4 t4 = *(const float4*)(q + base + (size_t)(q0 + r) * DD + d4);
        Qs[(d4 + 0) * 68 + r] = t4.x;
        Qs[(d4 + 1) * 68 + r] = t4.y;
        Qs[(d4 + 2) * 68 + r] = t4.z;
        Qs[(d4 + 3) * 68 + r] = t4.w;
    }

    float m_i[4], l_i[4], acc[4][4];
#pragma unroll
    for (int i = 0; i < 4; ++i) {
        m_i[i] = -INFINITY;
        l_i[i] = 0.0f;
#pragma unroll
        for (int j = 0; j < 4; ++j) acc[i][j] = 0.0f;
    }
    __syncthreads();

    for (int kt = 0; kt < SS / 64; ++kt) {
#pragma unroll
        for (int rep = 0; rep < 4; ++rep) {
            const int idx = tid + rep * 256;
            const int r = idx >> 4;
            const int d4 = (idx & 15) << 2;
            const size_t goff = base + (size_t)(kt * 64 + r) * DD + d4;
            const float4 kk = *(const float4*)(k + goff);
            Ks[(d4 + 0) * 68 + r] = kk.x;
            Ks[(d4 + 1) * 68 + r] = kk.y;
            Ks[(d4 + 2) * 68 + r] = kk.z;
            Ks[(d4 + 3) * 68 + r] = kk.w;
            const float4 vv = *(const float4*)(v + goff);
            *(float4*)&Vs[r * 68 + d4] = vv;
        }
        __syncthreads();

        float s[4][4];
#pragma unroll
        for (int i = 0; i < 4; ++i)
#pragma unroll
            for (int j = 0; j < 4; ++j) s[i][j] = 0.0f;

#pragma unroll
        for (int d = 0; d < 64; ++d) {
            const float4 a = *(const float4*)&Qs[d * 68 + ty * 4];
            const float4 bb = *(const float4*)&Ks[d * 68 + tx * 4];
            const float av[4] = {a.x, a.y, a.z, a.w};
            const float bv[4] = {bb.x, bb.y, bb.z, bb.w};
#pragma unroll
            for (int i = 0; i < 4; ++i)
#pragma unroll
                for (int j = 0; j < 4; ++j)
                    s[i][j] = fmaf(av[i], bv[j], s[i][j]);
        }

#pragma unroll
        for (int i = 0; i < 4; ++i) {
            float mx = -INFINITY;
#pragma unroll
            for (int j = 0; j < 4; ++j) {
                s[i][j] *= 0.125f;
                mx = fmaxf(mx, s[i][j]);
            }
#pragma unroll
            for (int off = 8; off >= 1; off >>= 1)
                mx = fmaxf(mx, __shfl_xor_sync(0xffffffffu, mx, off, 16));

            const float mnew = fmaxf(m_i[i], mx);
            const float corr = __expf(m_i[i] - mnew);
            float rsum = 0.0f;
#pragma unroll
            for (int j = 0; j < 4; ++j) {
                const float p = __expf(s[i][j] - mnew);
                s[i][j] = p;
                rsum += p;
            }
#pragma unroll
            for (int off = 8; off >= 1; off >>= 1)
                rsum += __shfl_xor_sync(0xffffffffu, rsum, off, 16);

            l_i[i] = l_i[i] * corr + rsum;
#pragma unroll
            for (int j = 0; j < 4; ++j) acc[i][j] *= corr;
            m_i[i] = mnew;
        }

#pragma unroll
        for (int j = 0; j < 4; ++j) {
            float4 pj;
            pj.x = s[0][j]; pj.y = s[1][j]; pj.z = s[2][j]; pj.w = s[3][j];
            *(float4*)&Ps[(tx * 4 + j) * 68 + ty * 4] = pj;
        }
        __syncthreads();

#pragma unroll
        for (int c = 0; c < 64; ++c) {
            const float4 a = *(const float4*)&Ps[c * 68 + ty * 4];
            const float4 bb = *(const float4*)&Vs[c * 68 + tx * 4];
            const float av[4] = {a.x, a.y, a.z, a.w};
            const float bv[4] = {bb.x, bb.y, bb.z, bb.w};
#pragma unroll
            for (int i = 0; i < 4; ++i)
#pragma unroll
                for (int j = 0; j < 4; ++j)
                    acc[i][j] = fmaf(av[i], bv[j], acc[i][j]);
        }
        __syncthreads();
    }

#pragma unroll
    for (int i = 0; i < 4; ++i) {
        const float inv = 1.0f / l_i[i];
        float4 o;
        o.x = acc[i][0] * inv; o.y = acc[i][1] * inv;
        o.z = acc[i][2] * inv; o.w = acc[i][3] * inv;
        *(float4*)(ctx + base + (size_t)(q0 + ty * 4 + i) * DD + tx * 4) = o;
    }
}

// ---------------- layernorm ---------------------------------------------------
__global__ __launch_bounds__(256) void ln_kernel(
    const float* __restrict__ x, const float* __restrict__ g,
    const float* __restrict__ bta, float* __restrict__ y)
{
    const int row = blockIdx.x;
    const float* xr = x + (size_t)row * DD;
    const int tid = threadIdx.x;
    const int lane = tid & 31;
    const int wid = tid >> 5;

    float vals[3];
#pragma unroll
    for (int i = 0; i < 3; ++i) vals[i] = xr[tid + i * 256];

    __shared__ float red[32];

    float sum = vals[0] + vals[1] + vals[2];
#pragma unroll
    for (int off = 16; off >= 1; off >>= 1)
        sum += __shfl_xor_sync(0xffffffffu, sum, off);
    if (lane == 0) red[wid] = sum;
    __syncthreads();
    if (tid < 32) {
        float t = (lane < 8) ? red[lane] : 0.0f;
#pragma unroll
        for (int off = 4; off >= 1; off >>= 1)
            t += __shfl_xor_sync(0xffffffffu, t, off);
        if (lane == 0) red[0] = t * (1.0f / DD);
    }
    __syncthreads();
    const float mu = red[0];
    __syncthreads();

    float vs = 0.0f;
#pragma unroll
    for (int i = 0; i < 3; ++i) {
        const float d = vals[i] - mu;
        vs += d * d;
    }
#pragma unroll
    for (int off = 16; off >= 1; off >>= 1)
        vs += __shfl_xor_sync(0xffffffffu, vs, off);
    if (lane == 0) red[wid] = vs;
    __syncthreads();
    if (tid < 32) {
        float t = (lane < 8) ? red[lane] : 0.0f;
#pragma unroll
        for (int off = 4; off >= 1; off >>= 1)
            t += __shfl_xor_sync(0xffffffffu, t, off);
        if (lane == 0) red[0] = t * (1.0f / DD);
    }
    __syncthreads();
    const float rstd = rsqrtf(red[0] + EPSL);

    float* yr = y + (size_t)row * DD;
#pragma unroll
    for (int i = 0; i < 3; ++i) {
        const int c = tid + i * 256;
        yr[c] = (vals[i] - mu) * rstd * g[c] + bta[c];
    }
}

// ---------------- launch ------------------------------------------------------
extern "C" void kernel_launch(void* const* d_in, const int* in_sizes, int n_in,
                              void* d_out, int out_size)
{
    (void)in_sizes; (void)n_in; (void)out_size;
    const float* Q    = (const float*)d_in[0];
    const float* K    = (const float*)d_in[1];
    const float* V    = (const float*)d_in[2];
    const float* Wq   = (const float*)d_in[3];
    const float* bq   = (const float*)d_in[4];
    const float* Wk   = (const float*)d_in[5];
    const float* bk   = (const float*)d_in[6];
    const float* Wv   = (const float*)d_in[7];
    const float* bv   = (const float*)d_in[8];
    const float* Wo   = (const float*)d_in[9];
    const float* bo   = (const float*)d_in[10];
    const float* ln_g = (const float*)d_in[11];
    const float* ln_b = (const float*)d_in[12];
    const float* W1   = (const float*)d_in[13];
    const float* b1   = (const float*)d_in[14];
    const float* W2   = (const float*)d_in[15];
    const float* b2   = (const float*)d_in[16];
    float* out = (float*)d_out;

    float* scr = nullptr;
    cudaGetSymbolAddress((void**)&scr, g_scratch);
    float* gq   = scr + OFF_Q;
    float* gk   = scr + OFF_K;
    float* gv   = scr + OFF_V;
    float* gctx = scr + OFF_CTX;
    float* gx1  = scr + OFF_X1;
    float* gh   = scr + OFF_H;
    float* gff  = scr + OFF_FF;

    const size_t attn_smem = 4 * 64 * 68 * sizeof(float);
    cudaFuncSetAttribute(attn_kernel, cudaFuncAttributeMaxDynamicSharedMemorySize,
                         (int)attn_smem);

    const dim3 blk(256);
    const dim3 g768(DD / 128, MR / 128);     // (6, 64)
    const dim3 g3072(DFF / 128, MR / 128);   // (24, 64)

    // QKV projections (tf32 mma.sync)
    mma_gemm<0><<<g768, blk>>>(Q, Wq, bq, nullptr, gq, MR, DD, DD);
    mma_gemm<0><<<g768, blk>>>(K, Wk, bk, nullptr, gk, MR, DD, DD);
    mma_gemm<0><<<g768, blk>>>(V, Wv, bv, nullptr, gv, MR, DD, DD);

    // attention
    const dim3 gattn(BB * HH, SS / 64);
    attn_kernel<<<gattn, blk, attn_smem>>>(gq, gk, gv, gctx);

    // output projection + residual
    mma_gemm<1><<<g768, blk>>>(gctx, Wo, bo, Q, gx1, MR, DD, DD);

    // layernorm
    ln_kernel<<<MR, blk>>>(gx1, ln_g, ln_b, gh);

    // FFN
    mma_gemm<2><<<g3072, blk>>>(gh, W1, b1, nullptr, gff, MR, DFF, DD);
    mma_gemm<0><<<g768, blk>>>(gff, W2, b2, nullptr, out, MR, DD, DFF);
}

// round 4
// speedup vs baseline: 2.7448x; 1.6559x over previous
#include <cuda_runtime.h>
#include <math.h>
#include <stdint.h>

// Problem constants
#define BB   4
#define SS   2048
#define DD   768
#define HH   12
#define DFF  3072
#define MR   8192          // B*S
#define EPSL 1e-5f

// ---------------- scratch ----------------------------------------------------
#define SZ_D   (MR * DD)
#define SZ_FF  (MR * DFF)
static __device__ float g_scratch[6 * SZ_D + SZ_FF];

#define OFF_Q    0
#define OFF_K    (1 * SZ_D)
#define OFF_V    (2 * SZ_D)
#define OFF_CTX  (3 * SZ_D)
#define OFF_X1   (4 * SZ_D)
#define OFF_H    (5 * SZ_D)
#define OFF_FF   (6 * SZ_D)

// ---------------- helpers ----------------------------------------------------
__device__ __forceinline__ float gelu_exact(float x) {
    return 0.5f * x * (1.0f + erff(x * 0.70710678118654752f));
}

__device__ __forceinline__ uint32_t tf32r(float x) {
    uint32_t u;
    asm("cvt.rna.tf32.f32 %0, %1;" : "=r"(u) : "f"(x));
    return u;
}

__device__ __forceinline__ void cpa16(uint32_t s, const void* g) {
    asm volatile("cp.async.cg.shared.global [%0], [%1], 16;" :: "r"(s), "l"(g));
}

__device__ __forceinline__ uint32_t smem_u32(const void* p) {
    uint32_t a;
    asm("{ .reg .u64 t; cvta.to.shared.u64 t, %1; cvt.u32.u64 %0, t; }"
        : "=r"(a) : "l"(p));
    return a;
}

// tf32 warp MMA: D(16x8) += A(16x8) * B(8x8)
__device__ __forceinline__ void mma8(float* c, const uint32_t* a, const uint32_t* b) {
    asm volatile(
        "mma.sync.aligned.m16n8k8.row.col.f32.tf32.tf32.f32 "
        "{%0,%1,%2,%3}, {%4,%5,%6,%7}, {%8,%9}, {%0,%1,%2,%3};"
        : "+f"(c[0]), "+f"(c[1]), "+f"(c[2]), "+f"(c[3])
        : "r"(a[0]), "r"(a[1]), "r"(a[2]), "r"(a[3]), "r"(b[0]), "r"(b[1]));
}

// ---------------- tf32 mma.sync GEMM (unchanged from round 3) ----------------
#define APAD 20
#define BPAD 136

template <int EPI>
__global__ __launch_bounds__(256) void mma_gemm(
    const float* __restrict__ A, const float* __restrict__ Bm,
    const float* __restrict__ bias, const float* __restrict__ res,
    float* __restrict__ C, int M, int N, int K)
{
    __shared__ float As[2][128][APAD];
    __shared__ float Bs[2][16][BPAD];

    const int tid = threadIdx.x;
    const int wid = tid >> 5;
    const int lane = tid & 31;
    const int wm = wid & 1;
    const int wn = wid >> 1;
    const int row4 = lane >> 2;
    const int kc = lane & 3;

    const int bm = blockIdx.y << 7;
    const int bn = blockIdx.x << 7;

    float acc[4][4][4];
#pragma unroll
    for (int i = 0; i < 4; ++i)
#pragma unroll
        for (int j = 0; j < 4; ++j)
#pragma unroll
            for (int q = 0; q < 4; ++q) acc[i][j][q] = 0.0f;

    const uint32_t sA = smem_u32(&As[0][0][0]);
    const uint32_t sB = smem_u32(&Bs[0][0][0]);
    const uint32_t stA = 128u * APAD * 4u;
    const uint32_t stB = 16u * BPAD * 4u;

    const int KT = K >> 4;

    auto load_stage = [&](int kt) {
        const int buf = kt & 1;
        const int k0 = kt << 4;
#pragma unroll
        for (int i = 0; i < 2; ++i) {
            const int c = tid + i * 256;
            {
                const int m = c >> 2, kq = c & 3;
                cpa16(sA + buf * stA + (uint32_t)(m * APAD + kq * 4) * 4u,
                      A + (size_t)(bm + m) * K + k0 + kq * 4);
            }
            {
                const int k = c >> 5, nq = c & 31;
                cpa16(sB + buf * stB + (uint32_t)(k * BPAD + nq * 4) * 4u,
                      Bm + (size_t)(k0 + k) * N + bn + nq * 4);
            }
        }
        asm volatile("cp.async.commit_group;" ::: "memory");
    };

    load_stage(0);

    for (int kt = 0; kt < KT; ++kt) {
        const int cur = kt & 1;
        if (kt + 1 < KT) {
            load_stage(kt + 1);
            asm volatile("cp.async.wait_group 1;" ::: "memory");
        } else {
            asm volatile("cp.async.wait_group 0;" ::: "memory");
        }
        __syncthreads();

#pragma unroll
        for (int kk = 0; kk < 2; ++kk) {
            const int kb = kk * 8;
            uint32_t au[4][4], bu[4][2];
#pragma unroll
            for (int mt = 0; mt < 4; ++mt) {
                const int m = wm * 64 + mt * 16 + row4;
                au[mt][0] = tf32r(As[cur][m][kb + kc]);
                au[mt][1] = tf32r(As[cur][m + 8][kb + kc]);
                au[mt][2] = tf32r(As[cur][m][kb + kc + 4]);
                au[mt][3] = tf32r(As[cur][m + 8][kb + kc + 4]);
            }
#pragma unroll
            for (int nt = 0; nt < 4; ++nt) {
                const int n = wn * 32 + nt * 8 + row4;
                bu[nt][0] = tf32r(Bs[cur][kb + kc][n]);
                bu[nt][1] = tf32r(Bs[cur][kb + kc + 4][n]);
            }
#pragma unroll
            for (int mt = 0; mt < 4; ++mt)
#pragma unroll
                for (int nt = 0; nt < 4; ++nt)
                    mma8(acc[mt][nt], au[mt], bu[nt]);
        }
        __syncthreads();
    }

#pragma unroll
    for (int mt = 0; mt < 4; ++mt) {
        const int r0 = bm + wm * 64 + mt * 16 + row4;
#pragma unroll
        for (int nt = 0; nt < 4; ++nt) {
            const int col = bn + wn * 32 + nt * 8 + kc * 2;
            const float b0 = bias[col], b1 = bias[col + 1];
            float v0 = acc[mt][nt][0] + b0;
            float v1 = acc[mt][nt][1] + b1;
            float v2 = acc[mt][nt][2] + b0;
            float v3 = acc[mt][nt][3] + b1;
            if (EPI == 1) {
                const float2 ra = *(const float2*)&res[(size_t)r0 * N + col];
                const float2 rb = *(const float2*)&res[(size_t)(r0 + 8) * N + col];
                v0 += ra.x; v1 += ra.y; v2 += rb.x; v3 += rb.y;
            }
            if (EPI == 2) {
                v0 = gelu_exact(v0); v1 = gelu_exact(v1);
                v2 = gelu_exact(v2); v3 = gelu_exact(v3);
            }
            *(float2*)&C[(size_t)r0 * N + col] = make_float2(v0, v1);
            *(float2*)&C[(size_t)(r0 + 8) * N + col] = make_float2(v2, v3);
        }
    }
}

// ---------------- tensor-core flash attention --------------------------------
// Block: 64 queries x one (b,h). 4 warps, each owns 16 query rows.
// Smem: Qs[64][68], Ks[2][64][68], Vs[2][64][72], Ps[64][68]
#define QPAD 68
#define VPAD 72
#define ATTN_SMEM ((64*QPAD + 2*64*QPAD + 2*64*VPAD + 64*QPAD) * 4)

__global__ __launch_bounds__(128) void attn_mma(
    const float* __restrict__ q, const float* __restrict__ k,
    const float* __restrict__ v, float* __restrict__ ctx)
{
    extern __shared__ float sm[];
    float* Qs = sm;                       // [64][68]
    float* Ks = Qs + 64 * QPAD;           // [2][64][68]
    float* Vs = Ks + 2 * 64 * QPAD;       // [2][64][72]
    float* Ps = Vs + 2 * 64 * VPAD;       // [64][68]

    const int bh = blockIdx.x;
    const int qt = blockIdx.y;
    const int b = bh / HH, h = bh % HH;
    const int tid = threadIdx.x;
    const int wid = tid >> 5;
    const int lane = tid & 31;
    const int g4 = lane >> 2;     // 0..7
    const int c4 = lane & 3;      // 0..3
    const size_t base = (size_t)(b * SS) * DD + h * 64;
    const int q0 = qt * 64;

    // load Q tile (natural layout)
#pragma unroll
    for (int i = 0; i < 8; ++i) {
        const int idx = tid + i * 128;
        const int r = idx >> 4, d4 = (idx & 15) << 2;
        const float4 t4 = *(const float4*)(q + base + (size_t)(q0 + r) * DD + d4);
        *(float4*)&Qs[r * QPAD + d4] = t4;
    }
    __syncthreads();

    // Q fragments in registers, pre-scaled by 1/sqrt(64)
    const int row0 = wid * 16 + g4;
    uint32_t qf[8][4];
#pragma unroll
    for (int ks = 0; ks < 8; ++ks) {
        const int d = ks * 8 + c4;
        qf[ks][0] = tf32r(0.125f * Qs[row0 * QPAD + d]);
        qf[ks][1] = tf32r(0.125f * Qs[(row0 + 8) * QPAD + d]);
        qf[ks][2] = tf32r(0.125f * Qs[row0 * QPAD + d + 4]);
        qf[ks][3] = tf32r(0.125f * Qs[(row0 + 8) * QPAD + d + 4]);
    }

    float oacc[8][4];
#pragma unroll
    for (int nt = 0; nt < 8; ++nt)
#pragma unroll
        for (int i = 0; i < 4; ++i) oacc[nt][i] = 0.0f;
    float m0 = -INFINITY, m1 = -INFINITY, l0 = 0.0f, l1 = 0.0f;

    auto prefetch = [&](int t) {
        const int buf = t & 1;
#pragma unroll
        for (int i = 0; i < 8; ++i) {
            const int idx = tid + i * 128;
            const int r = idx >> 4, d4 = (idx & 15) << 2;
            const size_t go = base + (size_t)(t * 64 + r) * DD + d4;
            cpa16(smem_u32(&Ks[(buf * 64 + r) * QPAD + d4]), k + go);
            cpa16(smem_u32(&Vs[(buf * 64 + r) * VPAD + d4]), v + go);
        }
        asm volatile("cp.async.commit_group;" ::: "memory");
    };

    prefetch(0);

    for (int t = 0; t < SS / 64; ++t) {
        asm volatile("cp.async.wait_group 0;" ::: "memory");
        __syncthreads();                         // data t visible; all warps done with t-1
        if (t + 1 < SS / 64) prefetch(t + 1);    // writes other buffer

        const float* Kb = &Ks[(t & 1) * 64 * QPAD];
        const float* Vb = &Vs[(t & 1) * 64 * VPAD];

        // S = Q K^T (scaled)
        float sacc[8][4];
#pragma unroll
        for (int nt = 0; nt < 8; ++nt)
#pragma unroll
            for (int i = 0; i < 4; ++i) sacc[nt][i] = 0.0f;

#pragma unroll
        for (int ks = 0; ks < 8; ++ks) {
            uint32_t bu[8][2];
            const int d = ks * 8 + c4;
#pragma unroll
            for (int nt = 0; nt < 8; ++nt) {
                const int c = nt * 8 + g4;
                bu[nt][0] = tf32r(Kb[c * QPAD + d]);
                bu[nt][1] = tf32r(Kb[c * QPAD + d + 4]);
            }
#pragma unroll
            for (int nt = 0; nt < 8; ++nt) mma8(sacc[nt], qf[ks], bu[nt]);
        }

        // online softmax (rows row0, row0+8; quad = lanes sharing g4)
        float mx0 = -INFINITY, mx1 = -INFINITY;
#pragma unroll
        for (int nt = 0; nt < 8; ++nt) {
            mx0 = fmaxf(mx0, fmaxf(sacc[nt][0], sacc[nt][1]));
            mx1 = fmaxf(mx1, fmaxf(sacc[nt][2], sacc[nt][3]));
        }
        mx0 = fmaxf(mx0, __shfl_xor_sync(0xffffffffu, mx0, 1));
        mx0 = fmaxf(mx0, __shfl_xor_sync(0xffffffffu, mx0, 2));
        mx1 = fmaxf(mx1, __shfl_xor_sync(0xffffffffu, mx1, 1));
        mx1 = fmaxf(mx1, __shfl_xor_sync(0xffffffffu, mx1, 2));

        const float mn0 = fmaxf(m0, mx0), mn1 = fmaxf(m1, mx1);
        const float cor0 = __expf(m0 - mn0), cor1 = __expf(m1 - mn1);
        float rs0 = 0.0f, rs1 = 0.0f;
#pragma unroll
        for (int nt = 0; nt < 8; ++nt) {
            sacc[nt][0] = __expf(sacc[nt][0] - mn0);
            sacc[nt][1] = __expf(sacc[nt][1] - mn0);
            sacc[nt][2] = __expf(sacc[nt][2] - mn1);
            sacc[nt][3] = __expf(sacc[nt][3] - mn1);
            rs0 += sacc[nt][0] + sacc[nt][1];
            rs1 += sacc[nt][2] + sacc[nt][3];
        }
        rs0 += __shfl_xor_sync(0xffffffffu, rs0, 1);
        rs0 += __shfl_xor_sync(0xffffffffu, rs0, 2);
        rs1 += __shfl_xor_sync(0xffffffffu, rs1, 1);
        rs1 += __shfl_xor_sync(0xffffffffu, rs1, 2);

        l0 = l0 * cor0 + rs0;
        l1 = l1 * cor1 + rs1;
        m0 = mn0; m1 = mn1;
#pragma unroll
        for (int nt = 0; nt < 8; ++nt) {
            oacc[nt][0] *= cor0; oacc[nt][1] *= cor0;
            oacc[nt][2] *= cor1; oacc[nt][3] *= cor1;
        }

        // P -> smem (C-fragment layout -> row-major)
#pragma unroll
        for (int nt = 0; nt < 8; ++nt) {
            const int col = nt * 8 + c4 * 2;
            *(float2*)&Ps[row0 * QPAD + col] = make_float2(sacc[nt][0], sacc[nt][1]);
            *(float2*)&Ps[(row0 + 8) * QPAD + col] = make_float2(sacc[nt][2], sacc[nt][3]);
        }
        __syncwarp();

        // O += P V
#pragma unroll
        for (int ks = 0; ks < 8; ++ks) {
            const int cc = ks * 8 + c4;
            uint32_t af[4];
            af[0] = tf32r(Ps[row0 * QPAD + cc]);
            af[1] = tf32r(Ps[(row0 + 8) * QPAD + cc]);
            af[2] = tf32r(Ps[row0 * QPAD + cc + 4]);
            af[3] = tf32r(Ps[(row0 + 8) * QPAD + cc + 4]);
            uint32_t bu[8][2];
#pragma unroll
            for (int nt = 0; nt < 8; ++nt) {
                const int dcol = nt * 8 + g4;
                bu[nt][0] = tf32r(Vb[cc * VPAD + dcol]);
                bu[nt][1] = tf32r(Vb[(cc + 4) * VPAD + dcol]);
            }
#pragma unroll
            for (int nt = 0; nt < 8; ++nt) mma8(oacc[nt], af, bu[nt]);
        }
    }

    // write ctx
    const float inv0 = 1.0f / l0, inv1 = 1.0f / l1;
#pragma unroll
    for (int nt = 0; nt < 8; ++nt) {
        const int col = nt * 8 + c4 * 2;
        *(float2*)(ctx + base + (size_t)(q0 + row0) * DD + col) =
            make_float2(oacc[nt][0] * inv0, oacc[nt][1] * inv0);
        *(float2*)(ctx + base + (size_t)(q0 + row0 + 8) * DD + col) =
            make_float2(oacc[nt][2] * inv1, oacc[nt][3] * inv1);
    }
}

// ---------------- layernorm ---------------------------------------------------
__global__ __launch_bounds__(256) void ln_kernel(
    const float* __restrict__ x, const float* __restrict__ g,
    const float* __restrict__ bta, float* __restrict__ y)
{
    const int row = blockIdx.x;
    const float* xr = x + (size_t)row * DD;
    const int tid = threadIdx.x;
    const int lane = tid & 31;
    const int wid = tid >> 5;

    float vals[3];
#pragma unroll
    for (int i = 0; i < 3; ++i) vals[i] = xr[tid + i * 256];

    __shared__ float red[32];

    float sum = vals[0] + vals[1] + vals[2];
#pragma unroll
    for (int off = 16; off >= 1; off >>= 1)
        sum += __shfl_xor_sync(0xffffffffu, sum, off);
    if (lane == 0) red[wid] = sum;
    __syncthreads();
    if (tid < 32) {
        float t = (lane < 8) ? red[lane] : 0.0f;
#pragma unroll
        for (int off = 4; off >= 1; off >>= 1)
            t += __shfl_xor_sync(0xffffffffu, t, off);
        if (lane == 0) red[0] = t * (1.0f / DD);
    }
    __syncthreads();
    const float mu = red[0];
    __syncthreads();

    float vs = 0.0f;
#pragma unroll
    for (int i = 0; i < 3; ++i) {
        const float d = vals[i] - mu;
        vs += d * d;
    }
#pragma unroll
    for (int off = 16; off >= 1; off >>= 1)
        vs += __shfl_xor_sync(0xffffffffu, vs, off);
    if (lane == 0) red[wid] = vs;
    __syncthreads();
    if (tid < 32) {
        float t = (lane < 8) ? red[lane] : 0.0f;
#pragma unroll
        for (int off = 4; off >= 1; off >>= 1)
            t += __shfl_xor_sync(0xffffffffu, t, off);
        if (lane == 0) red[0] = t * (1.0f / DD);
    }
    __syncthreads();
    const float rstd = rsqrtf(red[0] + EPSL);

    float* yr = y + (size_t)row * DD;
#pragma unroll
    for (int i = 0; i < 3; ++i) {
        const int c = tid + i * 256;
        yr[c] = (vals[i] - mu) * rstd * g[c] + bta[c];
    }
}

// ---------------- launch ------------------------------------------------------
extern "C" void kernel_launch(void* const* d_in, const int* in_sizes, int n_in,
                              void* d_out, int out_size)
{
    (void)in_sizes; (void)n_in; (void)out_size;
    const float* Q    = (const float*)d_in[0];
    const float* K    = (const float*)d_in[1];
    const float* V    = (const float*)d_in[2];
    const float* Wq   = (const float*)d_in[3];
    const float* bq   = (const float*)d_in[4];
    const float* Wk   = (const float*)d_in[5];
    const float* bk   = (const float*)d_in[6];
    const float* Wv   = (const float*)d_in[7];
    const float* bv   = (const float*)d_in[8];
    const float* Wo   = (const float*)d_in[9];
    const float* bo   = (const float*)d_in[10];
    const float* ln_g = (const float*)d_in[11];
    const float* ln_b = (const float*)d_in[12];
    const float* W1   = (const float*)d_in[13];
    const float* b1   = (const float*)d_in[14];
    const float* W2   = (const float*)d_in[15];
    const float* b2   = (const float*)d_in[16];
    float* out = (float*)d_out;

    float* scr = nullptr;
    cudaGetSymbolAddress((void**)&scr, g_scratch);
    float* gq   = scr + OFF_Q;
    float* gk   = scr + OFF_K;
    float* gv   = scr + OFF_V;
    float* gctx = scr + OFF_CTX;
    float* gx1  = scr + OFF_X1;
    float* gh   = scr + OFF_H;
    float* gff  = scr + OFF_FF;

    cudaFuncSetAttribute(attn_mma, cudaFuncAttributeMaxDynamicSharedMemorySize,
                         ATTN_SMEM);

    const dim3 blk(256);
    const dim3 g768(DD / 128, MR / 128);     // (6, 64)
    const dim3 g3072(DFF / 128, MR / 128);   // (24, 64)

    // QKV projections
    mma_gemm<0><<<g768, blk>>>(Q, Wq, bq, nullptr, gq, MR, DD, DD);
    mma_gemm<0><<<g768, blk>>>(K, Wk, bk, nullptr, gk, MR, DD, DD);
    mma_gemm<0><<<g768, blk>>>(V, Wv, bv, nullptr, gv, MR, DD, DD);

    // attention (tensor-core flash)
    const dim3 gattn(BB * HH, SS / 64);      // (48, 32)
    attn_mma<<<gattn, dim3(128), ATTN_SMEM>>>(gq, gk, gv, gctx);

    // output projection + residual
    mma_gemm<1><<<g768, blk>>>(gctx, Wo, bo, Q, gx1, MR, DD, DD);

    // layernorm
    ln_kernel<<<MR, blk>>>(gx1, ln_g, ln_b, gh);

    // FFN
    mma_gemm<2><<<g3072, blk>>>(gh, W1, b1, nullptr, gff, MR, DFF, DD);
    mma_gemm<0><<<g768, blk>>>(gff, W2, b2, nullptr, out, MR, DD, DFF);
}

// round 5
// speedup vs baseline: 2.9937x; 1.0907x over previous
#include <cuda_runtime.h>
#include <math.h>
#include <stdint.h>

// Problem constants
#define BB   4
#define SS   2048
#define DD   768
#define HH   12
#define DFF  3072
#define MR   8192          // B*S
#define EPSL 1e-5f

// ---------------- scratch ----------------------------------------------------
#define SZ_D   (MR * DD)
#define SZ_FF  (MR * DFF)
#define SZ_W   (DD * DD)
#define SZ_W1  (DD * DFF)
static __device__ float g_scratch[9 * SZ_D + SZ_FF + 4 * SZ_W + 2 * SZ_W1];

#define OFF_QR   0
#define OFF_KR   (OFF_QR + SZ_D)
#define OFF_VR   (OFF_KR + SZ_D)
#define OFF_Q    (OFF_VR + SZ_D)
#define OFF_K    (OFF_Q + SZ_D)
#define OFF_V    (OFF_K + SZ_D)
#define OFF_CTX  (OFF_V + SZ_D)
#define OFF_X1   (OFF_CTX + SZ_D)
#define OFF_H    (OFF_X1 + SZ_D)
#define OFF_FF   (OFF_H + SZ_D)
#define OFF_WQR  (OFF_FF + SZ_FF)
#define OFF_WKR  (OFF_WQR + SZ_W)
#define OFF_WVR  (OFF_WKR + SZ_W)
#define OFF_WOR  (OFF_WVR + SZ_W)
#define OFF_W1R  (OFF_WOR + SZ_W)
#define OFF_W2R  (OFF_W1R + SZ_W1)

// ---------------- helpers ----------------------------------------------------
__device__ __forceinline__ float gelu_exact(float x) {
    return 0.5f * x * (1.0f + erff(x * 0.70710678118654752f));
}

__device__ __forceinline__ float rtf32(float x) {
    uint32_t u;
    asm("cvt.rna.tf32.f32 %0, %1;" : "=r"(u) : "f"(x));
    return __uint_as_float(u);
}

__device__ __forceinline__ void cpa16(uint32_t s, const void* g) {
    asm volatile("cp.async.cg.shared.global [%0], [%1], 16;" :: "r"(s), "l"(g));
}

__device__ __forceinline__ uint32_t smem_u32(const void* p) {
    uint32_t a;
    asm("{ .reg .u64 t; cvta.to.shared.u64 t, %1; cvt.u32.u64 %0, t; }"
        : "=r"(a) : "l"(p));
    return a;
}

// tf32 warp MMA: D(16x8) += A(16x8) * B(8x8). Operands pre-rounded to tf32.
__device__ __forceinline__ void mma8f(float* c, const float* a, const float* b) {
    asm volatile(
        "mma.sync.aligned.m16n8k8.row.col.f32.tf32.tf32.f32 "
        "{%0,%1,%2,%3}, {%4,%5,%6,%7}, {%8,%9}, {%0,%1,%2,%3};"
        : "+f"(c[0]), "+f"(c[1]), "+f"(c[2]), "+f"(c[3])
        : "r"(__float_as_uint(a[0])), "r"(__float_as_uint(a[1])),
          "r"(__float_as_uint(a[2])), "r"(__float_as_uint(a[3])),
          "r"(__float_as_uint(b[0])), "r"(__float_as_uint(b[1])));
}

// ---------------- pre-pass: tf32 round-copy ----------------------------------
__global__ __launch_bounds__(256) void round_copy(
    const float* __restrict__ x, float* __restrict__ y, int n4)
{
    int i = blockIdx.x * 256 + threadIdx.x;
    if (i < n4) {
        float4 v = ((const float4*)x)[i];
        v.x = rtf32(v.x); v.y = rtf32(v.y); v.z = rtf32(v.z); v.w = rtf32(v.w);
        ((float4*)y)[i] = v;
    }
}

// ---------------- tf32 mma.sync GEMM -----------------------------------------
// C = A[MxK] @ B[KxN] + bias (+epi). A, B pre-rounded to tf32.
// EPI: 0 bias, 1 bias+residual, 2 bias+gelu.  RND: round outputs to tf32.
#define APAD 20
#define BPAD 136

template <int EPI, int RND>
__global__ __launch_bounds__(256) void mma_gemm(
    const float* __restrict__ A, const float* __restrict__ Bm,
    const float* __restrict__ bias, const float* __restrict__ res,
    float* __restrict__ C, int M, int N, int K)
{
    __shared__ float As[2][128][APAD];
    __shared__ float Bs[2][16][BPAD];

    const int tid = threadIdx.x;
    const int wid = tid >> 5;
    const int lane = tid & 31;
    const int wm = wid & 1;
    const int wn = wid >> 1;
    const int row4 = lane >> 2;
    const int kc = lane & 3;

    const int bm = blockIdx.y << 7;
    const int bn = blockIdx.x << 7;

    float acc[4][4][4];
#pragma unroll
    for (int i = 0; i < 4; ++i)
#pragma unroll
        for (int j = 0; j < 4; ++j)
#pragma unroll
            for (int q = 0; q < 4; ++q) acc[i][j][q] = 0.0f;

    const uint32_t sA = smem_u32(&As[0][0][0]);
    const uint32_t sB = smem_u32(&Bs[0][0][0]);
    const uint32_t stA = 128u * APAD * 4u;
    const uint32_t stB = 16u * BPAD * 4u;

    const int KT = K >> 4;

    auto load_stage = [&](int kt) {
        const int buf = kt & 1;
        const int k0 = kt << 4;
#pragma unroll
        for (int i = 0; i < 2; ++i) {
            const int c = tid + i * 256;
            {
                const int m = c >> 2, kq = c & 3;
                cpa16(sA + buf * stA + (uint32_t)(m * APAD + kq * 4) * 4u,
                      A + (size_t)(bm + m) * K + k0 + kq * 4);
            }
            {
                const int k = c >> 5, nq = c & 31;
                cpa16(sB + buf * stB + (uint32_t)(k * BPAD + nq * 4) * 4u,
                      Bm + (size_t)(k0 + k) * N + bn + nq * 4);
            }
        }
        asm volatile("cp.async.commit_group;" ::: "memory");
    };

    load_stage(0);

    for (int kt = 0; kt < KT; ++kt) {
        const int cur = kt & 1;
        if (kt + 1 < KT) {
            load_stage(kt + 1);
            asm volatile("cp.async.wait_group 1;" ::: "memory");
        } else {
            asm volatile("cp.async.wait_group 0;" ::: "memory");
        }
        __syncthreads();

#pragma unroll
        for (int kk = 0; kk < 2; ++kk) {
            const int kb = kk * 8;
            float au[4][4], bu[4][2];
#pragma unroll
            for (int mt = 0; mt < 4; ++mt) {
                const int m = wm * 64 + mt * 16 + row4;
                au[mt][0] = As[cur][m][kb + kc];
                au[mt][1] = As[cur][m + 8][kb + kc];
                au[mt][2] = As[cur][m][kb + kc + 4];
                au[mt][3] = As[cur][m + 8][kb + kc + 4];
            }
#pragma unroll
            for (int nt = 0; nt < 4; ++nt) {
                const int n = wn * 32 + nt * 8 + row4;
                bu[nt][0] = Bs[cur][kb + kc][n];
                bu[nt][1] = Bs[cur][kb + kc + 4][n];
            }
#pragma unroll
            for (int mt = 0; mt < 4; ++mt)
#pragma unroll
                for (int nt = 0; nt < 4; ++nt)
                    mma8f(acc[mt][nt], au[mt], bu[nt]);
        }
        __syncthreads();
    }

#pragma unroll
    for (int mt = 0; mt < 4; ++mt) {
        const int r0 = bm + wm * 64 + mt * 16 + row4;
#pragma unroll
        for (int nt = 0; nt < 4; ++nt) {
            const int col = bn + wn * 32 + nt * 8 + kc * 2;
            const float b0 = bias[col], b1 = bias[col + 1];
            float v0 = acc[mt][nt][0] + b0;
            float v1 = acc[mt][nt][1] + b1;
            float v2 = acc[mt][nt][2] + b0;
            float v3 = acc[mt][nt][3] + b1;
            if (EPI == 1) {
                const float2 ra = *(const float2*)&res[(size_t)r0 * N + col];
                const float2 rb = *(const float2*)&res[(size_t)(r0 + 8) * N + col];
                v0 += ra.x; v1 += ra.y; v2 += rb.x; v3 += rb.y;
            }
            if (EPI == 2) {
                v0 = gelu_exact(v0); v1 = gelu_exact(v1);
                v2 = gelu_exact(v2); v3 = gelu_exact(v3);
            }
            if (RND) {
                v0 = rtf32(v0); v1 = rtf32(v1);
                v2 = rtf32(v2); v3 = rtf32(v3);
            }
            *(float2*)&C[(size_t)r0 * N + col] = make_float2(v0, v1);
            *(float2*)&C[(size_t)(r0 + 8) * N + col] = make_float2(v2, v3);
        }
    }
}

// ---------------- tensor-core flash attention --------------------------------
// Block: 128 queries x one (b,h). 8 warps x 16 query rows. K/V tiles 64.
// q/k/v pre-rounded tf32. Smem: Ps[128][68] (also Q staging), Ks[2][64][68],
// Vs[2][64][72]  -> 106496 bytes.
#define QPAD 68
#define VPAD 72
#define ATTN_SMEM ((128 * QPAD + 2 * 64 * QPAD + 2 * 64 * VPAD) * 4)

__global__ __launch_bounds__(256) void attn_mma(
    const float* __restrict__ q, const float* __restrict__ k,
    const float* __restrict__ v, float* __restrict__ ctx)
{
    extern __shared__ float sm[];
    float* Ps = sm;                       // [128][68]  (Q staging, then P)
    float* Ks = Ps + 128 * QPAD;          // [2][64][68]
    float* Vs = Ks + 2 * 64 * QPAD;       // [2][64][72]

    const int bh = blockIdx.x;
    const int qt = blockIdx.y;
    const int b = bh / HH, h = bh % HH;
    const int tid = threadIdx.x;
    const int wid = tid >> 5;
    const int lane = tid & 31;
    const int g4 = lane >> 2;     // 0..7
    const int c4 = lane & 3;      // 0..3
    const size_t base = (size_t)(b * SS) * DD + h * 64;
    const int q0 = qt * 128;

    // stage Q tile (natural layout) in the P buffer
#pragma unroll
    for (int i = 0; i < 8; ++i) {
        const int idx = tid + i * 256;
        const int r = idx >> 4, d4 = (idx & 15) << 2;
        const float4 t4 = *(const float4*)(q + base + (size_t)(q0 + r) * DD + d4);
        *(float4*)&Ps[r * QPAD + d4] = t4;
    }
    __syncthreads();

    // Q fragments in registers, pre-scaled by 1/8 (exact exponent shift,
    // preserves tf32-ness)
    const int row0 = wid * 16 + g4;
    float qf[8][4];
#pragma unroll
    for (int ks = 0; ks < 8; ++ks) {
        const int d = ks * 8 + c4;
        qf[ks][0] = 0.125f * Ps[row0 * QPAD + d];
        qf[ks][1] = 0.125f * Ps[(row0 + 8) * QPAD + d];
        qf[ks][2] = 0.125f * Ps[row0 * QPAD + d + 4];
        qf[ks][3] = 0.125f * Ps[(row0 + 8) * QPAD + d + 4];
    }

    float oacc[8][4];
#pragma unroll
    for (int nt = 0; nt < 8; ++nt)
#pragma unroll
        for (int i = 0; i < 4; ++i) oacc[nt][i] = 0.0f;
    float m0 = -INFINITY, m1 = -INFINITY, l0 = 0.0f, l1 = 0.0f;

    auto prefetch = [&](int t) {
        const int buf = t & 1;
#pragma unroll
        for (int i = 0; i < 4; ++i) {
            const int idx = tid + i * 256;
            const int r = idx >> 4, d4 = (idx & 15) << 2;
            const size_t go = base + (size_t)(t * 64 + r) * DD + d4;
            cpa16(smem_u32(&Ks[(buf * 64 + r) * QPAD + d4]), k + go);
            cpa16(smem_u32(&Vs[(buf * 64 + r) * VPAD + d4]), v + go);
        }
        asm volatile("cp.async.commit_group;" ::: "memory");
    };

    prefetch(0);

    for (int t = 0; t < SS / 64; ++t) {
        asm volatile("cp.async.wait_group 0;" ::: "memory");
        __syncthreads();                         // t visible; all warps done with t-1
        if (t + 1 < SS / 64) prefetch(t + 1);    // other buffer

        const float* Kb = &Ks[(t & 1) * 64 * QPAD];
        const float* Vb = &Vs[(t & 1) * 64 * VPAD];

        // S = Q K^T (pre-scaled)
        float sacc[8][4];
#pragma unroll
        for (int nt = 0; nt < 8; ++nt)
#pragma unroll
            for (int i = 0; i < 4; ++i) sacc[nt][i] = 0.0f;

#pragma unroll
        for (int ks = 0; ks < 8; ++ks) {
            float bu[8][2];
            const int d = ks * 8 + c4;
#pragma unroll
            for (int nt = 0; nt < 8; ++nt) {
                const int c = nt * 8 + g4;
                bu[nt][0] = Kb[c * QPAD + d];
                bu[nt][1] = Kb[c * QPAD + d + 4];
            }
#pragma unroll
            for (int nt = 0; nt < 8; ++nt) mma8f(sacc[nt], qf[ks], bu[nt]);
        }

        // online softmax (rows row0, row0+8; quad reductions)
        float mx0 = -INFINITY, mx1 = -INFINITY;
#pragma unroll
        for (int nt = 0; nt < 8; ++nt) {
            mx0 = fmaxf(mx0, fmaxf(sacc[nt][0], sacc[nt][1]));
            mx1 = fmaxf(mx1, fmaxf(sacc[nt][2], sacc[nt][3]));
        }
        mx0 = fmaxf(mx0, __shfl_xor_sync(0xffffffffu, mx0, 1));
        mx0 = fmaxf(mx0, __shfl_xor_sync(0xffffffffu, mx0, 2));
        mx1 = fmaxf(mx1, __shfl_xor_sync(0xffffffffu, mx1, 1));
        mx1 = fmaxf(mx1, __shfl_xor_sync(0xffffffffu, mx1, 2));

        const float mn0 = fmaxf(m0, mx0), mn1 = fmaxf(m1, mx1);
        const float cor0 = __expf(m0 - mn0), cor1 = __expf(m1 - mn1);
        float rs0 = 0.0f, rs1 = 0.0f;
#pragma unroll
        for (int nt = 0; nt < 8; ++nt) {
            sacc[nt][0] = __expf(sacc[nt][0] - mn0);
            sacc[nt][1] = __expf(sacc[nt][1] - mn0);
            sacc[nt][2] = __expf(sacc[nt][2] - mn1);
            sacc[nt][3] = __expf(sacc[nt][3] - mn1);
            rs0 += sacc[nt][0] + sacc[nt][1];
            rs1 += sacc[nt][2] + sacc[nt][3];
        }
        rs0 += __shfl_xor_sync(0xffffffffu, rs0, 1);
        rs0 += __shfl_xor_sync(0xffffffffu, rs0, 2);
        rs1 += __shfl_xor_sync(0xffffffffu, rs1, 1);
        rs1 += __shfl_xor_sync(0xffffffffu, rs1, 2);

        l0 = l0 * cor0 + rs0;
        l1 = l1 * cor1 + rs1;
        m0 = mn0; m1 = mn1;
#pragma unroll
        for (int nt = 0; nt < 8; ++nt) {
            oacc[nt][0] *= cor0; oacc[nt][1] *= cor0;
            oacc[nt][2] *= cor1; oacc[nt][3] *= cor1;
        }

        // P -> smem, rounded to tf32 at write (C-frag -> row-major)
#pragma unroll
        for (int nt = 0; nt < 8; ++nt) {
            const int col = nt * 8 + c4 * 2;
            *(float2*)&Ps[row0 * QPAD + col] =
                make_float2(rtf32(sacc[nt][0]), rtf32(sacc[nt][1]));
            *(float2*)&Ps[(row0 + 8) * QPAD + col] =
                make_float2(rtf32(sacc[nt][2]), rtf32(sacc[nt][3]));
        }
        __syncwarp();

        // O += P V
#pragma unroll
        for (int ks = 0; ks < 8; ++ks) {
            const int cc = ks * 8 + c4;
            float af[4];
            af[0] = Ps[row0 * QPAD + cc];
            af[1] = Ps[(row0 + 8) * QPAD + cc];
            af[2] = Ps[row0 * QPAD + cc + 4];
            af[3] = Ps[(row0 + 8) * QPAD + cc + 4];
            float bu[8][2];
#pragma unroll
            for (int nt = 0; nt < 8; ++nt) {
                const int dcol = nt * 8 + g4;
                bu[nt][0] = Vb[cc * VPAD + dcol];
                bu[nt][1] = Vb[(cc + 4) * VPAD + dcol];
            }
#pragma unroll
            for (int nt = 0; nt < 8; ++nt) mma8f(oacc[nt], af, bu[nt]);
        }
    }

    // write ctx (rounded: feeds Wo GEMM as A operand)
    const float inv0 = 1.0f / l0, inv1 = 1.0f / l1;
#pragma unroll
    for (int nt = 0; nt < 8; ++nt) {
        const int col = nt * 8 + c4 * 2;
        *(float2*)(ctx + base + (size_t)(q0 + row0) * DD + col) =
            make_float2(rtf32(oacc[nt][0] * inv0), rtf32(oacc[nt][1] * inv0));
        *(float2*)(ctx + base + (size_t)(q0 + row0 + 8) * DD + col) =
            make_float2(rtf32(oacc[nt][2] * inv1), rtf32(oacc[nt][3] * inv1));
    }
}

// ---------------- layernorm (writes tf32-rounded output) ---------------------
__global__ __launch_bounds__(256) void ln_kernel(
    const float* __restrict__ x, const float* __restrict__ g,
    const float* __restrict__ bta, float* __restrict__ y)
{
    const int row = blockIdx.x;
    const float* xr = x + (size_t)row * DD;
    const int tid = threadIdx.x;
    const int lane = tid & 31;
    const int wid = tid >> 5;

    float vals[3];
#pragma unroll
    for (int i = 0; i < 3; ++i) vals[i] = xr[tid + i * 256];

    __shared__ float red[32];

    float sum = vals[0] + vals[1] + vals[2];
#pragma unroll
    for (int off = 16; off >= 1; off >>= 1)
        sum += __shfl_xor_sync(0xffffffffu, sum, off);
    if (lane == 0) red[wid] = sum;
    __syncthreads();
    if (tid < 32) {
        float t = (lane < 8) ? red[lane] : 0.0f;
#pragma unroll
        for (int off = 4; off >= 1; off >>= 1)
            t += __shfl_xor_sync(0xffffffffu, t, off);
        if (lane == 0) red[0] = t * (1.0f / DD);
    }
    __syncthreads();
    const float mu = red[0];
    __syncthreads();

    float vs = 0.0f;
#pragma unroll
    for (int i = 0; i < 3; ++i) {
        const float d = vals[i] - mu;
        vs += d * d;
    }
#pragma unroll
    for (int off = 16; off >= 1; off >>= 1)
        vs += __shfl_xor_sync(0xffffffffu, vs, off);
    if (lane == 0) red[wid] = vs;
    __syncthreads();
    if (tid < 32) {
        float t = (lane < 8) ? red[lane] : 0.0f;
#pragma unroll
        for (int off = 4; off >= 1; off >>= 1)
            t += __shfl_xor_sync(0xffffffffu, t, off);
        if (lane == 0) red[0] = t * (1.0f / DD);
    }
    __syncthreads();
    const float rstd = rsqrtf(red[0] + EPSL);

    float* yr = y + (size_t)row * DD;
#pragma unroll
    for (int i = 0; i < 3; ++i) {
        const int c = tid + i * 256;
        yr[c] = rtf32((vals[i] - mu) * rstd * g[c] + bta[c]);
    }
}

// ---------------- launch ------------------------------------------------------
extern "C" void kernel_launch(void* const* d_in, const int* in_sizes, int n_in,
                              void* d_out, int out_size)
{
    (void)in_sizes; (void)n_in; (void)out_size;
    const float* Q    = (const float*)d_in[0];
    const float* K    = (const float*)d_in[1];
    const float* V    = (const float*)d_in[2];
    const float* Wq   = (const float*)d_in[3];
    const float* bq   = (const float*)d_in[4];
    const float* Wk   = (const float*)d_in[5];
    const float* bk   = (const float*)d_in[6];
    const float* Wv   = (const float*)d_in[7];
    const float* bv   = (const float*)d_in[8];
    const float* Wo   = (const float*)d_in[9];
    const float* bo   = (const float*)d_in[10];
    const float* ln_g = (const float*)d_in[11];
    const float* ln_b = (const float*)d_in[12];
    const float* W1   = (const float*)d_in[13];
    const float* b1   = (const float*)d_in[14];
    const float* W2   = (const float*)d_in[15];
    const float* b2   = (const float*)d_in[16];
    float* out = (float*)d_out;

    float* scr = nullptr;
    cudaGetSymbolAddress((void**)&scr, g_scratch);
    float* qr   = scr + OFF_QR;
    float* kr   = scr + OFF_KR;
    float* vr   = scr + OFF_VR;
    float* gq   = scr + OFF_Q;
    float* gk   = scr + OFF_K;
    float* gv   = scr + OFF_V;
    float* gctx = scr + OFF_CTX;
    float* gx1  = scr + OFF_X1;
    float* gh   = scr + OFF_H;
    float* gff  = scr + OFF_FF;
    float* Wqr  = scr + OFF_WQR;
    float* Wkr  = scr + OFF_WKR;
    float* Wvr  = scr + OFF_WVR;
    float* Wor  = scr + OFF_WOR;
    float* W1r  = scr + OFF_W1R;
    float* W2r  = scr + OFF_W2R;

    cudaFuncSetAttribute(attn_mma, cudaFuncAttributeMaxDynamicSharedMemorySize,
                         ATTN_SMEM);

    const dim3 blk(256);
    const dim3 g768(DD / 128, MR / 128);     // (6, 64)
    const dim3 g3072(DFF / 128, MR / 128);   // (24, 64)

    // pre-pass: tf32 round-copy raw inputs + weights (same layout)
    round_copy<<<SZ_D / 1024, blk>>>(Q, qr, SZ_D / 4);
    round_copy<<<SZ_D / 1024, blk>>>(K, kr, SZ_D / 4);
    round_copy<<<SZ_D / 1024, blk>>>(V, vr, SZ_D / 4);
    round_copy<<<SZ_W / 1024, blk>>>(Wq, Wqr, SZ_W / 4);
    round_copy<<<SZ_W / 1024, blk>>>(Wk, Wkr, SZ_W / 4);
    round_copy<<<SZ_W / 1024, blk>>>(Wv, Wvr, SZ_W / 4);
    round_copy<<<SZ_W / 1024, blk>>>(Wo, Wor, SZ_W / 4);
    round_copy<<<SZ_W1 / 1024, blk>>>(W1, W1r, SZ_W1 / 4);
    round_copy<<<SZ_W1 / 1024, blk>>>(W2, W2r, SZ_W1 / 4);

    // QKV projections (outputs rounded -> attention operands)
    mma_gemm<0, 1><<<g768, blk>>>(qr, Wqr, bq, nullptr, gq, MR, DD, DD);
    mma_gemm<0, 1><<<g768, blk>>>(kr, Wkr, bk, nullptr, gk, MR, DD, DD);
    mma_gemm<0, 1><<<g768, blk>>>(vr, Wvr, bv, nullptr, gv, MR, DD, DD);

    // attention (tensor-core flash, 128q x 8 warps)
    const dim3 gattn(BB * HH, SS / 128);     // (48, 16)
    attn_mma<<<gattn, blk, ATTN_SMEM>>>(gq, gk, gv, gctx);

    // output projection + residual (exact Q residual; output fp32 for LN)
    mma_gemm<1, 0><<<g768, blk>>>(gctx, Wor, bo, Q, gx1, MR, DD, DD);

    // layernorm (writes rounded h)
    ln_kernel<<<MR, blk>>>(gx1, ln_g, ln_b, gh);

    // FFN (gelu output rounded; final output exact fp32)
    mma_gemm<2, 1><<<g3072, blk>>>(gh, W1r, b1, nullptr, gff, MR, DFF, DD);
    mma_gemm<0, 0><<<g768, blk>>>(gff, W2r, b2, nullptr, out, MR, DD, DFF);
}

// round 6
// speedup vs baseline: 3.0870x; 1.0312x over previous
#include <cuda_runtime.h>
#include <math.h>
#include <stdint.h>

// Problem constants
#define BB   4
#define SS   2048
#define DD   768
#define HH   12
#define DFF  3072
#define MR   8192          // B*S
#define EPSL 1e-5f

// ---------------- scratch ----------------------------------------------------
#define SZ_D   (MR * DD)
#define SZ_FF  (MR * DFF)
#define SZ_W   (DD * DD)
#define SZ_W1  (DD * DFF)
static __device__ float g_scratch[9 * SZ_D + SZ_FF + 4 * SZ_W + 2 * SZ_W1];

#define OFF_QR   0
#define OFF_KR   (OFF_QR + SZ_D)
#define OFF_VR   (OFF_KR + SZ_D)
#define OFF_Q    (OFF_VR + SZ_D)
#define OFF_K    (OFF_Q + SZ_D)
#define OFF_V    (OFF_K + SZ_D)
#define OFF_CTX  (OFF_V + SZ_D)
#define OFF_X1   (OFF_CTX + SZ_D)
#define OFF_H    (OFF_X1 + SZ_D)
#define OFF_FF   (OFF_H + SZ_D)
#define OFF_WQR  (OFF_FF + SZ_FF)
#define OFF_WKR  (OFF_WQR + SZ_W)
#define OFF_WVR  (OFF_WKR + SZ_W)
#define OFF_WOR  (OFF_WVR + SZ_W)
#define OFF_W1R  (OFF_WOR + SZ_W)
#define OFF_W2R  (OFF_W1R + SZ_W1)

// ---------------- helpers ----------------------------------------------------
__device__ __forceinline__ float gelu_exact(float x) {
    return 0.5f * x * (1.0f + erff(x * 0.70710678118654752f));
}

__device__ __forceinline__ float rtf32(float x) {
    uint32_t u;
    asm("cvt.rna.tf32.f32 %0, %1;" : "=r"(u) : "f"(x));
    return __uint_as_float(u);
}

__device__ __forceinline__ void cpa16(uint32_t s, const void* g) {
    asm volatile("cp.async.cg.shared.global [%0], [%1], 16;" :: "r"(s), "l"(g));
}

__device__ __forceinline__ uint32_t smem_u32(const void* p) {
    uint32_t a;
    asm("{ .reg .u64 t; cvta.to.shared.u64 t, %1; cvt.u32.u64 %0, t; }"
        : "=r"(a) : "l"(p));
    return a;
}

// tf32 warp MMA: D(16x8) += A(16x8) * B(8x8). Operands pre-rounded to tf32.
__device__ __forceinline__ void mma8f(float* c, const float* a, const float* b) {
    asm volatile(
        "mma.sync.aligned.m16n8k8.row.col.f32.tf32.tf32.f32 "
        "{%0,%1,%2,%3}, {%4,%5,%6,%7}, {%8,%9}, {%0,%1,%2,%3};"
        : "+f"(c[0]), "+f"(c[1]), "+f"(c[2]), "+f"(c[3])
        : "r"(__float_as_uint(a[0])), "r"(__float_as_uint(a[1])),
          "r"(__float_as_uint(a[2])), "r"(__float_as_uint(a[3])),
          "r"(__float_as_uint(b[0])), "r"(__float_as_uint(b[1])));
}

// ---------------- pre-pass: tf32 round-copy ----------------------------------
__global__ __launch_bounds__(256) void round_copy(
    const float* __restrict__ x, float* __restrict__ y, int n4)
{
    int i = blockIdx.x * 256 + threadIdx.x;
    if (i < n4) {
        float4 v = ((const float4*)x)[i];
        v.x = rtf32(v.x); v.y = rtf32(v.y); v.z = rtf32(v.z); v.w = rtf32(v.w);
        ((float4*)y)[i] = v;
    }
}

// ---------------- GEMM v2: 64x64 warp tiles, 4-stage cp.async ----------------
// C = A[MxK] @ B[KxN] + bias (+epi). Inputs pre-rounded tf32.
// CTAN = CTA N-tile (128 or 256); threads = CTAN; warps 2(M) x CTAN/64(N).
// gridDim.z selects a (A,B,bias,res,C) set -> lets QKV run as one launch.
struct GSet { const float* A; const float* Bm; const float* bias;
              const float* res; float* C; };
struct GSet3 { GSet s[3]; };

#define APAD   20
#define NSTG   4

template <int CTAN, int EPI, int RND>
__global__ __launch_bounds__(CTAN, (CTAN == 128) ? 2 : 1) void gemm2(
    GSet3 P, int M, int N, int K)
{
    constexpr int BPAD = CTAN + 8;           // 136 or 264 (both = 8 mod 32)
    constexpr int ASTG = 128 * APAD;         // floats per A stage
    constexpr int BSTG = 16 * BPAD;          // floats per B stage

    extern __shared__ float sm[];
    float* As = sm;                          // [4][128][APAD]
    float* Bs = sm + NSTG * ASTG;            // [4][16][BPAD]

    const GSet gs = P.s[blockIdx.z];
    const float* __restrict__ A = gs.A;
    const float* __restrict__ Bm = gs.Bm;
    const float* __restrict__ bias = gs.bias;
    const float* __restrict__ res = gs.res;
    float* __restrict__ C = gs.C;

    const int tid = threadIdx.x;
    const int wid = tid >> 5;
    const int lane = tid & 31;
    const int g4 = lane >> 2;     // 0..7
    const int kc = lane & 3;      // 0..3
    const int wm = wid & 1;
    const int wn = wid >> 1;

    const int bm = blockIdx.y << 7;
    const int bn = blockIdx.x * CTAN;

    float acc[4][8][4];
#pragma unroll
    for (int i = 0; i < 4; ++i)
#pragma unroll
        for (int j = 0; j < 8; ++j)
#pragma unroll
            for (int q = 0; q < 4; ++q) acc[i][j][q] = 0.0f;

    const uint32_t sAb = smem_u32(As);
    const uint32_t sBb = smem_u32(Bs);

    const int KT = K >> 4;

    auto load_stage = [&](int kt) {
        const int st = kt & 3;
        const int k0 = kt << 4;
        const uint32_t aB = sAb + (uint32_t)st * ASTG * 4u;
        const uint32_t bB = sBb + (uint32_t)st * BSTG * 4u;
#pragma unroll
        for (int i = 0; i < 512 / CTAN; ++i) {       // A: 512 float4
            const int c = tid + i * CTAN;
            const int m = c >> 2, kq = c & 3;
            cpa16(aB + (uint32_t)(m * APAD + kq * 4) * 4u,
                  A + (size_t)(bm + m) * K + k0 + kq * 4);
        }
#pragma unroll
        for (int i = 0; i < 4; ++i) {                // B: 4*CTAN float4
            const int c = tid + i * CTAN;
            const int kr = c / (CTAN >> 2), nq = c % (CTAN >> 2);
            cpa16(bB + (uint32_t)(kr * BPAD + nq * 4) * 4u,
                  Bm + (size_t)(k0 + kr) * N + bn + nq * 4);
        }
        asm volatile("cp.async.commit_group;" ::: "memory");
    };

    load_stage(0); load_stage(1); load_stage(2);

    for (int kt = 0; kt < KT; ++kt) {
        const int rem = KT - 1 - kt;
        if (rem >= 2)      asm volatile("cp.async.wait_group 2;" ::: "memory");
        else if (rem == 1) asm volatile("cp.async.wait_group 1;" ::: "memory");
        else               asm volatile("cp.async.wait_group 0;" ::: "memory");
        __syncthreads();
        if (kt + 3 < KT) load_stage(kt + 3);   // slot (kt+3)&3 == (kt-1)&3: free

        const int st = kt & 3;
        const float* Ast = As + st * ASTG;
        const float* Bst = Bs + st * BSTG;

#pragma unroll
        for (int kk = 0; kk < 2; ++kk) {
            const int kb = kk * 8;
            float au[4][4], bu[8][2];
#pragma unroll
            for (int mt = 0; mt < 4; ++mt) {
                const int m = wm * 64 + mt * 16 + g4;
                au[mt][0] = Ast[m * APAD + kb + kc];
                au[mt][1] = Ast[(m + 8) * APAD + kb + kc];
                au[mt][2] = Ast[m * APAD + kb + kc + 4];
                au[mt][3] = Ast[(m + 8) * APAD + kb + kc + 4];
            }
#pragma unroll
            for (int nt = 0; nt < 8; ++nt) {
                const int n = wn * 64 + nt * 8 + g4;
                bu[nt][0] = Bst[(kb + kc) * BPAD + n];
                bu[nt][1] = Bst[(kb + kc + 4) * BPAD + n];
            }
#pragma unroll
            for (int mt = 0; mt < 4; ++mt)
#pragma unroll
                for (int nt = 0; nt < 8; ++nt)
                    mma8f(acc[mt][nt], au[mt], bu[nt]);
        }
    }

    // epilogue
#pragma unroll
    for (int mt = 0; mt < 4; ++mt) {
        const int r0 = bm + wm * 64 + mt * 16 + g4;
#pragma unroll
        for (int nt = 0; nt < 8; ++nt) {
            const int col = bn + wn * 64 + nt * 8 + kc * 2;
            const float b0 = bias[col], b1 = bias[col + 1];
            float v0 = acc[mt][nt][0] + b0;
            float v1 = acc[mt][nt][1] + b1;
            float v2 = acc[mt][nt][2] + b0;
            float v3 = acc[mt][nt][3] + b1;
            if (EPI == 1) {
                const float2 ra = *(const float2*)&res[(size_t)r0 * N + col];
                const float2 rb = *(const float2*)&res[(size_t)(r0 + 8) * N + col];
                v0 += ra.x; v1 += ra.y; v2 += rb.x; v3 += rb.y;
            }
            if (EPI == 2) {
                v0 = gelu_exact(v0); v1 = gelu_exact(v1);
                v2 = gelu_exact(v2); v3 = gelu_exact(v3);
            }
            if (RND) {
                v0 = rtf32(v0); v1 = rtf32(v1);
                v2 = rtf32(v2); v3 = rtf32(v3);
            }
            *(float2*)&C[(size_t)r0 * N + col] = make_float2(v0, v1);
            *(float2*)&C[(size_t)(r0 + 8) * N + col] = make_float2(v2, v3);
        }
    }
}

#define GEMM_SMEM_W ((NSTG * (128 * APAD + 16 * (256 + 8))) * 4)
#define GEMM_SMEM_N ((NSTG * (128 * APAD + 16 * (128 + 8))) * 4)

// ---------------- tensor-core flash attention (unchanged from R5) ------------
#define QPAD 68
#define VPAD 72
#define ATTN_SMEM ((128 * QPAD + 2 * 64 * QPAD + 2 * 64 * VPAD) * 4)

__global__ __launch_bounds__(256) void attn_mma(
    const float* __restrict__ q, const float* __restrict__ k,
    const float* __restrict__ v, float* __restrict__ ctx)
{
    extern __shared__ float sm[];
    float* Ps = sm;                       // [128][68]  (Q staging, then P)
    float* Ks = Ps + 128 * QPAD;          // [2][64][68]
    float* Vs = Ks + 2 * 64 * QPAD;       // [2][64][72]

    const int bh = blockIdx.x;
    const int qt = blockIdx.y;
    const int b = bh / HH, h = bh % HH;
    const int tid = threadIdx.x;
    const int wid = tid >> 5;
    const int lane = tid & 31;
    const int g4 = lane >> 2;
    const int c4 = lane & 3;
    const size_t base = (size_t)(b * SS) * DD + h * 64;
    const int q0 = qt * 128;

#pragma unroll
    for (int i = 0; i < 8; ++i) {
        const int idx = tid + i * 256;
        const int r = idx >> 4, d4 = (idx & 15) << 2;
        const float4 t4 = *(const float4*)(q + base + (size_t)(q0 + r) * DD + d4);
        *(float4*)&Ps[r * QPAD + d4] = t4;
    }
    __syncthreads();

    const int row0 = wid * 16 + g4;
    float qf[8][4];
#pragma unroll
    for (int ks = 0; ks < 8; ++ks) {
        const int d = ks * 8 + c4;
        qf[ks][0] = 0.125f * Ps[row0 * QPAD + d];
        qf[ks][1] = 0.125f * Ps[(row0 + 8) * QPAD + d];
        qf[ks][2] = 0.125f * Ps[row0 * QPAD + d + 4];
        qf[ks][3] = 0.125f * Ps[(row0 + 8) * QPAD + d + 4];
    }

    float oacc[8][4];
#pragma unroll
    for (int nt = 0; nt < 8; ++nt)
#pragma unroll
        for (int i = 0; i < 4; ++i) oacc[nt][i] = 0.0f;
    float m0 = -INFINITY, m1 = -INFINITY, l0 = 0.0f, l1 = 0.0f;

    auto prefetch = [&](int t) {
        const int buf = t & 1;
#pragma unroll
        for (int i = 0; i < 4; ++i) {
            const int idx = tid + i * 256;
            const int r = idx >> 4, d4 = (idx & 15) << 2;
            const size_t go = base + (size_t)(t * 64 + r) * DD + d4;
            cpa16(smem_u32(&Ks[(buf * 64 + r) * QPAD + d4]), k + go);
            cpa16(smem_u32(&Vs[(buf * 64 + r) * VPAD + d4]), v + go);
        }
        asm volatile("cp.async.commit_group;" ::: "memory");
    };

    prefetch(0);

    for (int t = 0; t < SS / 64; ++t) {
        asm volatile("cp.async.wait_group 0;" ::: "memory");
        __syncthreads();
        if (t + 1 < SS / 64) prefetch(t + 1);

        const float* Kb = &Ks[(t & 1) * 64 * QPAD];
        const float* Vb = &Vs[(t & 1) * 64 * VPAD];

        float sacc[8][4];
#pragma unroll
        for (int nt = 0; nt < 8; ++nt)
#pragma unroll
            for (int i = 0; i < 4; ++i) sacc[nt][i] = 0.0f;

#pragma unroll
        for (int ks = 0; ks < 8; ++ks) {
            float bu[8][2];
            const int d = ks * 8 + c4;
#pragma unroll
            for (int nt = 0; nt < 8; ++nt) {
                const int c = nt * 8 + g4;
                bu[nt][0] = Kb[c * QPAD + d];
                bu[nt][1] = Kb[c * QPAD + d + 4];
            }
#pragma unroll
            for (int nt = 0; nt < 8; ++nt) mma8f(sacc[nt], qf[ks], bu[nt]);
        }

        float mx0 = -INFINITY, mx1 = -INFINITY;
#pragma unroll
        for (int nt = 0; nt < 8; ++nt) {
            mx0 = fmaxf(mx0, fmaxf(sacc[nt][0], sacc[nt][1]));
            mx1 = fmaxf(mx1, fmaxf(sacc[nt][2], sacc[nt][3]));
        }
        mx0 = fmaxf(mx0, __shfl_xor_sync(0xffffffffu, mx0, 1));
        mx0 = fmaxf(mx0, __shfl_xor_sync(0xffffffffu, mx0, 2));
        mx1 = fmaxf(mx1, __shfl_xor_sync(0xffffffffu, mx1, 1));
        mx1 = fmaxf(mx1, __shfl_xor_sync(0xffffffffu, mx1, 2));

        const float mn0 = fmaxf(m0, mx0), mn1 = fmaxf(m1, mx1);
        const float cor0 = __expf(m0 - mn0), cor1 = __expf(m1 - mn1);
        float rs0 = 0.0f, rs1 = 0.0f;
#pragma unroll
        for (int nt = 0; nt < 8; ++nt) {
            sacc[nt][0] = __expf(sacc[nt][0] - mn0);
            sacc[nt][1] = __expf(sacc[nt][1] - mn0);
            sacc[nt][2] = __expf(sacc[nt][2] - mn1);
            sacc[nt][3] = __expf(sacc[nt][3] - mn1);
            rs0 += sacc[nt][0] + sacc[nt][1];
            rs1 += sacc[nt][2] + sacc[nt][3];
        }
        rs0 += __shfl_xor_sync(0xffffffffu, rs0, 1);
        rs0 += __shfl_xor_sync(0xffffffffu, rs0, 2);
        rs1 += __shfl_xor_sync(0xffffffffu, rs1, 1);
        rs1 += __shfl_xor_sync(0xffffffffu, rs1, 2);

        l0 = l0 * cor0 + rs0;
        l1 = l1 * cor1 + rs1;
        m0 = mn0; m1 = mn1;
#pragma unroll
        for (int nt = 0; nt < 8; ++nt) {
            oacc[nt][0] *= cor0; oacc[nt][1] *= cor0;
            oacc[nt][2] *= cor1; oacc[nt][3] *= cor1;
        }

#pragma unroll
        for (int nt = 0; nt < 8; ++nt) {
            const int col = nt * 8 + c4 * 2;
            *(float2*)&Ps[row0 * QPAD + col] =
                make_float2(rtf32(sacc[nt][0]), rtf32(sacc[nt][1]));
            *(float2*)&Ps[(row0 + 8) * QPAD + col] =
                make_float2(rtf32(sacc[nt][2]), rtf32(sacc[nt][3]));
        }
        __syncwarp();

#pragma unroll
        for (int ks = 0; ks < 8; ++ks) {
            const int cc = ks * 8 + c4;
            float af[4];
            af[0] = Ps[row0 * QPAD + cc];
            af[1] = Ps[(row0 + 8) * QPAD + cc];
            af[2] = Ps[row0 * QPAD + cc + 4];
            af[3] = Ps[(row0 + 8) * QPAD + cc + 4];
            float bu[8][2];
#pragma unroll
            for (int nt = 0; nt < 8; ++nt) {
                const int dcol = nt * 8 + g4;
                bu[nt][0] = Vb[cc * VPAD + dcol];
                bu[nt][1] = Vb[(cc + 4) * VPAD + dcol];
            }
#pragma unroll
            for (int nt = 0; nt < 8; ++nt) mma8f(oacc[nt], af, bu[nt]);
        }
    }

    const float inv0 = 1.0f / l0, inv1 = 1.0f / l1;
#pragma unroll
    for (int nt = 0; nt < 8; ++nt) {
        const int col = nt * 8 + c4 * 2;
        *(float2*)(ctx + base + (size_t)(q0 + row0) * DD + col) =
            make_float2(rtf32(oacc[nt][0] * inv0), rtf32(oacc[nt][1] * inv0));
        *(float2*)(ctx + base + (size_t)(q0 + row0 + 8) * DD + col) =
            make_float2(rtf32(oacc[nt][2] * inv1), rtf32(oacc[nt][3] * inv1));
    }
}

// ---------------- layernorm (writes tf32-rounded output) ---------------------
__global__ __launch_bounds__(256) void ln_kernel(
    const float* __restrict__ x, const float* __restrict__ g,
    const float* __restrict__ bta, float* __restrict__ y)
{
    const int row = blockIdx.x;
    const float* xr = x + (size_t)row * DD;
    const int tid = threadIdx.x;
    const int lane = tid & 31;
    const int wid = tid >> 5;

    float vals[3];
#pragma unroll
    for (int i = 0; i < 3; ++i) vals[i] = xr[tid + i * 256];

    __shared__ float red[32];

    float sum = vals[0] + vals[1] + vals[2];
#pragma unroll
    for (int off = 16; off >= 1; off >>= 1)
        sum += __shfl_xor_sync(0xffffffffu, sum, off);
    if (lane == 0) red[wid] = sum;
    __syncthreads();
    if (tid < 32) {
        float t = (lane < 8) ? red[lane] : 0.0f;
#pragma unroll
        for (int off = 4; off >= 1; off >>= 1)
            t += __shfl_xor_sync(0xffffffffu, t, off);
        if (lane == 0) red[0] = t * (1.0f / DD);
    }
    __syncthreads();
    const float mu = red[0];
    __syncthreads();

    float vs = 0.0f;
#pragma unroll
    for (int i = 0; i < 3; ++i) {
        const float d = vals[i] - mu;
        vs += d * d;
    }
#pragma unroll
    for (int off = 16; off >= 1; off >>= 1)
        vs += __shfl_xor_sync(0xffffffffu, vs, off);
    if (lane == 0) red[wid] = vs;
    __syncthreads();
    if (tid < 32) {
        float t = (lane < 8) ? red[lane] : 0.0f;
#pragma unroll
        for (int off = 4; off >= 1; off >>= 1)
            t += __shfl_xor_sync(0xffffffffu, t, off);
        if (lane == 0) red[0] = t * (1.0f / DD);
    }
    __syncthreads();
    const float rstd = rsqrtf(red[0] + EPSL);

    float* yr = y + (size_t)row * DD;
#pragma unroll
    for (int i = 0; i < 3; ++i) {
        const int c = tid + i * 256;
        yr[c] = rtf32((vals[i] - mu) * rstd * g[c] + bta[c]);
    }
}

// ---------------- launch ------------------------------------------------------
extern "C" void kernel_launch(void* const* d_in, const int* in_sizes, int n_in,
                              void* d_out, int out_size)
{
    (void)in_sizes; (void)n_in; (void)out_size;
    const float* Q    = (const float*)d_in[0];
    const float* K    = (const float*)d_in[1];
    const float* V    = (const float*)d_in[2];
    const float* Wq   = (const float*)d_in[3];
    const float* bq   = (const float*)d_in[4];
    const float* Wk   = (const float*)d_in[5];
    const float* bk   = (const float*)d_in[6];
    const float* Wv   = (const float*)d_in[7];
    const float* bv   = (const float*)d_in[8];
    const float* Wo   = (const float*)d_in[9];
    const float* bo   = (const float*)d_in[10];
    const float* ln_g = (const float*)d_in[11];
    const float* ln_b = (const float*)d_in[12];
    const float* W1   = (const float*)d_in[13];
    const float* b1   = (const float*)d_in[14];
    const float* W2   = (const float*)d_in[15];
    const float* b2   = (const float*)d_in[16];
    float* out = (float*)d_out;

    float* scr = nullptr;
    cudaGetSymbolAddress((void**)&scr, g_scratch);
    float* qr   = scr + OFF_QR;
    float* kr   = scr + OFF_KR;
    float* vr   = scr + OFF_VR;
    float* gq   = scr + OFF_Q;
    float* gk   = scr + OFF_K;
    float* gv   = scr + OFF_V;
    float* gctx = scr + OFF_CTX;
    float* gx1  = scr + OFF_X1;
    float* gh   = scr + OFF_H;
    float* gff  = scr + OFF_FF;
    float* Wqr  = scr + OFF_WQR;
    float* Wkr  = scr + OFF_WKR;
    float* Wvr  = scr + OFF_WVR;
    float* Wor  = scr + OFF_WOR;
    float* W1r  = scr + OFF_W1R;
    float* W2r  = scr + OFF_W2R;

    cudaFuncSetAttribute(attn_mma, cudaFuncAttributeMaxDynamicSharedMemorySize,
                         ATTN_SMEM);
    cudaFuncSetAttribute(gemm2<256, 0, 1>,
                         cudaFuncAttributeMaxDynamicSharedMemorySize, GEMM_SMEM_W);
    cudaFuncSetAttribute(gemm2<256, 2, 1>,
                         cudaFuncAttributeMaxDynamicSharedMemorySize, GEMM_SMEM_W);
    cudaFuncSetAttribute(gemm2<128, 1, 0>,
                         cudaFuncAttributeMaxDynamicSharedMemorySize, GEMM_SMEM_N);
    cudaFuncSetAttribute(gemm2<128, 0, 0>,
                         cudaFuncAttributeMaxDynamicSharedMemorySize, GEMM_SMEM_N);

    const dim3 blk(256);

    // pre-pass: tf32 round-copy raw inputs + weights
    round_copy<<<SZ_D / 1024, blk>>>(Q, qr, SZ_D / 4);
    round_copy<<<SZ_D / 1024, blk>>>(K, kr, SZ_D / 4);
    round_copy<<<SZ_D / 1024, blk>>>(V, vr, SZ_D / 4);
    round_copy<<<SZ_W / 1024, blk>>>(Wq, Wqr, SZ_W / 4);
    round_copy<<<SZ_W / 1024, blk>>>(Wk, Wkr, SZ_W / 4);
    round_copy<<<SZ_W / 1024, blk>>>(Wv, Wvr, SZ_W / 4);
    round_copy<<<SZ_W / 1024, blk>>>(Wo, Wor, SZ_W / 4);
    round_copy<<<SZ_W1 / 1024, blk>>>(W1, W1r, SZ_W1 / 4);
    round_copy<<<SZ_W1 / 1024, blk>>>(W2, W2r, SZ_W1 / 4);

    // QKV projections: one wide launch, z selects the GEMM
    {
        GSet3 P;
        P.s[0] = { qr, Wqr, bq, nullptr, gq };
        P.s[1] = { kr, Wkr, bk, nullptr, gk };
        P.s[2] = { vr, Wvr, bv, nullptr, gv };
        gemm2<256, 0, 1><<<dim3(DD / 256, MR / 128, 3), blk, GEMM_SMEM_W>>>(
            P, MR, DD, DD);
    }

    // attention
    const dim3 gattn(BB * HH, SS / 128);
    attn_mma<<<gattn, blk, ATTN_SMEM>>>(gq, gk, gv, gctx);

    // output projection + residual (narrow, 2 CTAs/SM)
    {
        GSet3 P;
        P.s[0] = { gctx, Wor, bo, Q, gx1 };
        P.s[1] = P.s[0]; P.s[2] = P.s[0];
        gemm2<128, 1, 0><<<dim3(DD / 128, MR / 128, 1), dim3(128), GEMM_SMEM_N>>>(
            P, MR, DD, DD);
    }

    // layernorm
    ln_kernel<<<MR, blk>>>(gx1, ln_g, ln_b, gh);

    // FFN1 (wide) + FFN2 (narrow)
    {
        GSet3 P;
        P.s[0] = { gh, W1r, b1, nullptr, gff };
        P.s[1] = P.s[0]; P.s[2] = P.s[0];
        gemm2<256, 2, 1><<<dim3(DFF / 256, MR / 128, 1), blk, GEMM_SMEM_W>>>(
            P, MR, DFF, DD);
    }
    {
        GSet3 P;
        P.s[0] = { gff, W2r, b2, nullptr, out };
        P.s[1] = P.s[0]; P.s[2] = P.s[0];
        gemm2<128, 0, 0><<<dim3(DD / 128, MR / 128, 1), dim3(128), GEMM_SMEM_N>>>(
            P, MR, DD, DFF);
    }
}

// round 7
// speedup vs baseline: 5.1264x; 1.6606x over previous
#include <cuda_runtime.h>
#include <cuda_fp16.h>
#include <math.h>
#include <stdint.h>

// Problem constants
#define BB   4
#define SS   2048
#define DD   768
#define HH   12
#define DFF  3072
#define MR   8192          // B*S
#define EPSL 1e-5f

#define SZ_D   (MR * DD)
#define SZ_FF  (MR * DFF)
#define SZ_W   (DD * DD)
#define SZ_W1  (DD * DFF)

// ---------------- scratch ----------------------------------------------------
// half pool: qr,kr,vr,gq,gk,gv,gctx,gh (8*SZ_D) + gff (SZ_FF) + 4 W + 2 W1
static __device__ __align__(256) __half g_half[8 * SZ_D + SZ_FF + 4 * SZ_W + 2 * SZ_W1];
static __device__ __align__(256) float g_x1[SZ_D];

#define HO_QR   0
#define HO_KR   (HO_QR + SZ_D)
#define HO_VR   (HO_KR + SZ_D)
#define HO_GQ   (HO_VR + SZ_D)
#define HO_GK   (HO_GQ + SZ_D)
#define HO_GV   (HO_GK + SZ_D)
#define HO_CTX  (HO_GV + SZ_D)
#define HO_H    (HO_CTX + SZ_D)
#define HO_FF   (HO_H + SZ_D)
#define HO_WQ   (HO_FF + SZ_FF)
#define HO_WK   (HO_WQ + SZ_W)
#define HO_WV   (HO_WK + SZ_W)
#define HO_WO   (HO_WV + SZ_W)
#define HO_W1   (HO_WO + SZ_W)
#define HO_W2   (HO_W1 + SZ_W1)

// ---------------- helpers ----------------------------------------------------
__device__ __forceinline__ float gelu_exact(float x) {
    return 0.5f * x * (1.0f + erff(x * 0.70710678118654752f));
}

__device__ __forceinline__ void cpa16(uint32_t s, const void* g) {
    asm volatile("cp.async.cg.shared.global [%0], [%1], 16;" :: "r"(s), "l"(g));
}

__device__ __forceinline__ uint32_t smem_u32(const void* p) {
    uint32_t a;
    asm("{ .reg .u64 t; cvta.to.shared.u64 t, %1; cvt.u32.u64 %0, t; }"
        : "=r"(a) : "l"(p));
    return a;
}

#define LDSM4(r0, r1, r2, r3, addr)                                            \
    asm volatile("ldmatrix.sync.aligned.m8n8.x4.shared.b16 {%0,%1,%2,%3}, [%4];" \
        : "=r"(r0), "=r"(r1), "=r"(r2), "=r"(r3) : "r"(addr))

#define LDSM4T(r0, r1, r2, r3, addr)                                           \
    asm volatile("ldmatrix.sync.aligned.m8n8.x4.trans.shared.b16 {%0,%1,%2,%3}, [%4];" \
        : "=r"(r0), "=r"(r1), "=r"(r2), "=r"(r3) : "r"(addr))

// fp16 warp MMA: D(16x8,f32) += A(16x16,f16) * B(16x8,f16)
__device__ __forceinline__ void mma16(float* c, const uint32_t* a, const uint32_t* b) {
    asm volatile(
        "mma.sync.aligned.m16n8k16.row.col.f32.f16.f16.f32 "
        "{%0,%1,%2,%3}, {%4,%5,%6,%7}, {%8,%9}, {%0,%1,%2,%3};"
        : "+f"(c[0]), "+f"(c[1]), "+f"(c[2]), "+f"(c[3])
        : "r"(a[0]), "r"(a[1]), "r"(a[2]), "r"(a[3]), "r"(b[0]), "r"(b[1]));
}

__device__ __forceinline__ uint32_t pack2h(float lo, float hi) {
    __half2 h = __floats2half2_rn(lo, hi);
    return *(uint32_t*)&h;
}

// ---------------- pre-pass: fp32 -> fp16 -------------------------------------
__global__ __launch_bounds__(256) void f2h(
    const float* __restrict__ x, __half* __restrict__ y, int n4)
{
    int i = blockIdx.x * 256 + threadIdx.x;
    if (i < n4) {
        const float4 v = ((const float4*)x)[i];
        uint2 o;
        o.x = pack2h(v.x, v.y);
        o.y = pack2h(v.z, v.w);
        ((uint2*)y)[i] = o;
    }
}

// ---------------- fp16 mma GEMM ----------------------------------------------
// C = A[MxK] @ B[KxN] + bias (+epi). A,B half. CTAN in {128,256}, threads=CTAN.
// EPI: 0 bias, 1 bias+residual(fp32), 2 bias+gelu.  OUTH: 1 -> C is half.
struct GSet { const __half* A; const __half* Bm; const float* bias;
              const float* res; void* C; };
struct GSet3 { GSet s[3]; };

#define APADH 24               // 16 k-halves + 8 pad; 48B row stride
#define ASTGH (128 * APADH)
#define NSTG  4

template <int CTAN, int EPI, int OUTH>
__global__ __launch_bounds__(CTAN, (CTAN == 128) ? 2 : 1) void hgemm(
    GSet3 P, int M, int N, int K)
{
    constexpr int BPADH = CTAN + 8;
    constexpr int BSTGH = 16 * BPADH;
    constexpr int NQ = CTAN / 8;           // 16B chunks per B row

    extern __shared__ __half hsm[];
    __half* As = hsm;                      // [4][128][APADH]
    __half* Bs = hsm + NSTG * ASTGH;       // [4][16][BPADH]

    const GSet gs = P.s[blockIdx.z];
    const __half* __restrict__ A = gs.A;
    const __half* __restrict__ Bm = gs.Bm;
    const float* __restrict__ bias = gs.bias;
    const float* __restrict__ res = gs.res;

    const int tid = threadIdx.x;
    const int wid = tid >> 5;
    const int lane = tid & 31;
    const int wm = wid & 1;
    const int wn = wid >> 1;

    const int bm = blockIdx.y << 7;
    const int bn = blockIdx.x * CTAN;

    float acc[4][8][4];
#pragma unroll
    for (int i = 0; i < 4; ++i)
#pragma unroll
        for (int j = 0; j < 8; ++j)
#pragma unroll
            for (int q = 0; q < 4; ++q) acc[i][j][q] = 0.0f;

    const uint32_t sAb = smem_u32(As);
    const uint32_t sBb = smem_u32(Bs);

    const int KT = K >> 4;

    auto load_stage = [&](int kt) {
        const int st = kt & 3;
        const int k0 = kt << 4;
        const uint32_t aB = sAb + (uint32_t)st * ASTGH * 2u;
        const uint32_t bB = sBb + (uint32_t)st * BSTGH * 2u;
#pragma unroll
        for (int i = 0; i < 256 / CTAN; ++i) {        // A: 256 chunks
            const int c = tid + i * CTAN;
            const int m = c >> 1, hc = (c & 1) * 8;
            cpa16(aB + (uint32_t)(m * APADH + hc) * 2u,
                  A + (size_t)(bm + m) * K + k0 + hc);
        }
#pragma unroll
        for (int i = 0; i < 2; ++i) {                 // B: 2*CTAN chunks
            const int c = tid + i * CTAN;
            const int kr = c / NQ, nq = c % NQ;
            cpa16(bB + (uint32_t)(kr * BPADH + nq * 8) * 2u,
                  Bm + (size_t)(k0 + kr) * N + bn + nq * 8);
        }
        asm volatile("cp.async.commit_group;" ::: "memory");
    };

    load_stage(0); load_stage(1); load_stage(2);

    for (int kt = 0; kt < KT; ++kt) {
        const int rem = KT - 1 - kt;
        if (rem >= 2)      asm volatile("cp.async.wait_group 2;" ::: "memory");
        else if (rem == 1) asm volatile("cp.async.wait_group 1;" ::: "memory");
        else               asm volatile("cp.async.wait_group 0;" ::: "memory");
        __syncthreads();
        if (kt + 3 < KT) load_stage(kt + 3);

        const int st = kt & 3;
        const uint32_t aS = sAb + (uint32_t)st * ASTGH * 2u;
        const uint32_t bS = sBb + (uint32_t)st * BSTGH * 2u;

        uint32_t au[4][4], bu[8][2];
#pragma unroll
        for (int mt = 0; mt < 4; ++mt) {
            const int row = wm * 64 + mt * 16 + (lane & 15);
            const int kh = (lane >> 4) * 8;
            LDSM4(au[mt][0], au[mt][1], au[mt][2], au[mt][3],
                  aS + (uint32_t)(row * APADH + kh) * 2u);
        }
#pragma unroll
        for (int ng = 0; ng < 4; ++ng) {
            const int n0 = wn * 64 + ng * 16;
            const uint32_t ad = bS +
                (uint32_t)((lane & 15) * BPADH + n0 + (lane >> 4) * 8) * 2u;
            LDSM4T(bu[2 * ng][0], bu[2 * ng][1],
                   bu[2 * ng + 1][0], bu[2 * ng + 1][1], ad);
        }
#pragma unroll
        for (int mt = 0; mt < 4; ++mt)
#pragma unroll
            for (int nt = 0; nt < 8; ++nt)
                mma16(acc[mt][nt], au[mt], bu[nt]);
    }

    // epilogue
#pragma unroll
    for (int mt = 0; mt < 4; ++mt) {
        const int r0 = bm + wm * 64 + mt * 16 + (lane >> 2);
#pragma unroll
        for (int nt = 0; nt < 8; ++nt) {
            const int col = bn + wn * 64 + nt * 8 + (lane & 3) * 2;
            const float b0 = bias[col], b1 = bias[col + 1];
            float v0 = acc[mt][nt][0] + b0;
            float v1 = acc[mt][nt][1] + b1;
            float v2 = acc[mt][nt][2] + b0;
            float v3 = acc[mt][nt][3] + b1;
            if (EPI == 1) {
                const float2 ra = *(const float2*)&res[(size_t)r0 * N + col];
                const float2 rb = *(const float2*)&res[(size_t)(r0 + 8) * N + col];
                v0 += ra.x; v1 += ra.y; v2 += rb.x; v3 += rb.y;
            }
            if (EPI == 2) {
                v0 = gelu_exact(v0); v1 = gelu_exact(v1);
                v2 = gelu_exact(v2); v3 = gelu_exact(v3);
            }
            if (OUTH) {
                __half* C = (__half*)gs.C;
                *(uint32_t*)&C[(size_t)r0 * N + col] = pack2h(v0, v1);
                *(uint32_t*)&C[(size_t)(r0 + 8) * N + col] = pack2h(v2, v3);
            } else {
                float* C = (float*)gs.C;
                *(float2*)&C[(size_t)r0 * N + col] = make_float2(v0, v1);
                *(float2*)&C[(size_t)(r0 + 8) * N + col] = make_float2(v2, v3);
            }
        }
    }
}

#define GEMM_SMEM_W ((NSTG * (ASTGH + 16 * (256 + 8))) * 2)
#define GEMM_SMEM_N ((NSTG * (ASTGH + 16 * (128 + 8))) * 2)

// ---------------- fp16 tensor-core flash attention ---------------------------
// 128 queries x one (b,h) per CTA; 8 warps x 16 rows; kv tiles of 64.
// P lives entirely in registers (S C-frag -> PV A-frag remap).
#define KPADH 72              // 64 + 8 halves; 144B row stride
#define ATTN_SMEM ((128 * KPADH + 2 * 64 * KPADH + 2 * 64 * KPADH) * 2)

__global__ __launch_bounds__(256) void attn_h(
    const __half* __restrict__ q, const __half* __restrict__ k,
    const __half* __restrict__ v, __half* __restrict__ ctx)
{
    extern __shared__ __half asm_[];
    __half* Qs = asm_;                        // [128][72]
    __half* Ks = Qs + 128 * KPADH;            // [2][64][72]
    __half* Vs = Ks + 2 * 64 * KPADH;         // [2][64][72]

    const int bh = blockIdx.x;
    const int qt = blockIdx.y;
    const int b = bh / HH, h = bh % HH;
    const int tid = threadIdx.x;
    const int wid = tid >> 5;
    const int lane = tid & 31;
    const size_t base = (size_t)(b * SS) * DD + h * 64;
    const int q0 = qt * 128;

    // stage Q (8 half-chunks of 16B per row)
#pragma unroll
    for (int i = 0; i < 4; ++i) {
        const int idx = tid + i * 256;
        const int r = idx >> 3, hc = idx & 7;
        cpa16(smem_u32(Qs + r * KPADH + hc * 8),
              q + base + (size_t)(q0 + r) * DD + hc * 8);
    }
    asm volatile("cp.async.commit_group; cp.async.wait_group 0;" ::: "memory");
    __syncthreads();

    // Q fragments, scaled by 1/8 (exact in fp16)
    uint32_t qf[4][4];
    {
        const int row = wid * 16 + (lane & 15);
        const __half2 s8 = __float2half2_rn(0.125f);
#pragma unroll
        for (int dk = 0; dk < 4; ++dk) {
            LDSM4(qf[dk][0], qf[dk][1], qf[dk][2], qf[dk][3],
                  smem_u32(Qs + row * KPADH + dk * 16 + (lane >> 4) * 8));
#pragma unroll
            for (int j = 0; j < 4; ++j) {
                __half2 t = __hmul2(*(__half2*)&qf[dk][j], s8);
                qf[dk][j] = *(uint32_t*)&t;
            }
        }
    }

    float oacc[8][4];
#pragma unroll
    for (int nt = 0; nt < 8; ++nt)
#pragma unroll
        for (int i = 0; i < 4; ++i) oacc[nt][i] = 0.0f;
    float m0 = -INFINITY, m1 = -INFINITY, l0 = 0.0f, l1 = 0.0f;

    auto prefetch = [&](int t) {
        const int buf = t & 1;
#pragma unroll
        for (int i = 0; i < 2; ++i) {
            const int idx = tid + i * 256;
            const int r = idx >> 3, hc = idx & 7;
            const size_t go = base + (size_t)(t * 64 + r) * DD + hc * 8;
            cpa16(smem_u32(Ks + (buf * 64 + r) * KPADH + hc * 8), k + go);
            cpa16(smem_u32(Vs + (buf * 64 + r) * KPADH + hc * 8), v + go);
        }
        asm volatile("cp.async.commit_group;" ::: "memory");
    };

    prefetch(0);

    for (int t = 0; t < SS / 64; ++t) {
        asm volatile("cp.async.wait_group 0;" ::: "memory");
        __syncthreads();
        if (t + 1 < SS / 64) prefetch(t + 1);

        const uint32_t kb = smem_u32(Ks + (t & 1) * 64 * KPADH);
        const uint32_t vb = smem_u32(Vs + (t & 1) * 64 * KPADH);

        // S = Q K^T
        float sacc[8][4];
#pragma unroll
        for (int nt = 0; nt < 8; ++nt)
#pragma unroll
            for (int i = 0; i < 4; ++i) sacc[nt][i] = 0.0f;

#pragma unroll
        for (int dk = 0; dk < 4; ++dk) {
            uint32_t ku[8][2];
#pragma unroll
            for (int cg = 0; cg < 4; ++cg) {
                const int row = cg * 16 + (lane & 7) + ((lane >> 4) * 8);
                const int dh = dk * 16 + ((lane >> 3) & 1) * 8;
                LDSM4(ku[2 * cg][0], ku[2 * cg][1],
                      ku[2 * cg + 1][0], ku[2 * cg + 1][1],
                      kb + (uint32_t)(row * KPADH + dh) * 2u);
            }
#pragma unroll
            for (int ct = 0; ct < 8; ++ct) mma16(sacc[ct], qf[dk], ku[ct]);
        }

        // online softmax (rows wid*16+(lane>>2), +8; quad reductions)
        float mx0 = -INFINITY, mx1 = -INFINITY;
#pragma unroll
        for (int nt = 0; nt < 8; ++nt) {
            mx0 = fmaxf(mx0, fmaxf(sacc[nt][0], sacc[nt][1]));
            mx1 = fmaxf(mx1, fmaxf(sacc[nt][2], sacc[nt][3]));
        }
        mx0 = fmaxf(mx0, __shfl_xor_sync(0xffffffffu, mx0, 1));
        mx0 = fmaxf(mx0, __shfl_xor_sync(0xffffffffu, mx0, 2));
        mx1 = fmaxf(mx1, __shfl_xor_sync(0xffffffffu, mx1, 1));
        mx1 = fmaxf(mx1, __shfl_xor_sync(0xffffffffu, mx1, 2));

        const float mn0 = fmaxf(m0, mx0), mn1 = fmaxf(m1, mx1);
        const float cor0 = __expf(m0 - mn0), cor1 = __expf(m1 - mn1);
        float rs0 = 0.0f, rs1 = 0.0f;
#pragma unroll
        for (int nt = 0; nt < 8; ++nt) {
            sacc[nt][0] = __expf(sacc[nt][0] - mn0);
            sacc[nt][1] = __expf(sacc[nt][1] - mn0);
            sacc[nt][2] = __expf(sacc[nt][2] - mn1);
            sacc[nt][3] = __expf(sacc[nt][3] - mn1);
            rs0 += sacc[nt][0] + sacc[nt][1];
            rs1 += sacc[nt][2] + sacc[nt][3];
        }
        rs0 += __shfl_xor_sync(0xffffffffu, rs0, 1);
        rs0 += __shfl_xor_sync(0xffffffffu, rs0, 2);
        rs1 += __shfl_xor_sync(0xffffffffu, rs1, 1);
        rs1 += __shfl_xor_sync(0xffffffffu, rs1, 2);

        l0 = l0 * cor0 + rs0;
        l1 = l1 * cor1 + rs1;
        m0 = mn0; m1 = mn1;
#pragma unroll
        for (int nt = 0; nt < 8; ++nt) {
            oacc[nt][0] *= cor0; oacc[nt][1] *= cor0;
            oacc[nt][2] *= cor1; oacc[nt][3] *= cor1;
        }

        // O += P V  (P stays in registers: S C-frag -> A-frag remap)
#pragma unroll
        for (int cc = 0; cc < 4; ++cc) {
            uint32_t af[4];
            af[0] = pack2h(sacc[2 * cc][0], sacc[2 * cc][1]);
            af[1] = pack2h(sacc[2 * cc][2], sacc[2 * cc][3]);
            af[2] = pack2h(sacc[2 * cc + 1][0], sacc[2 * cc + 1][1]);
            af[3] = pack2h(sacc[2 * cc + 1][2], sacc[2 * cc + 1][3]);

            uint32_t vu[8][2];
#pragma unroll
            for (int dg = 0; dg < 4; ++dg) {
                const int row = cc * 16 + (lane & 15);
                const int dh = dg * 16 + (lane >> 4) * 8;
                LDSM4T(vu[2 * dg][0], vu[2 * dg][1],
                       vu[2 * dg + 1][0], vu[2 * dg + 1][1],
                       vb + (uint32_t)(row * KPADH + dh) * 2u);
            }
#pragma unroll
            for (int dt = 0; dt < 8; ++dt) mma16(oacc[dt], af, vu[dt]);
        }
    }

    // write ctx (half)
    const float inv0 = 1.0f / l0, inv1 = 1.0f / l1;
    const int row0 = wid * 16 + (lane >> 2);
#pragma unroll
    for (int dt = 0; dt < 8; ++dt) {
        const int col = dt * 8 + (lane & 3) * 2;
        *(uint32_t*)(ctx + base + (size_t)(q0 + row0) * DD + col) =
            pack2h(oacc[dt][0] * inv0, oacc[dt][1] * inv0);
        *(uint32_t*)(ctx + base + (size_t)(q0 + row0 + 8) * DD + col) =
            pack2h(oacc[dt][2] * inv1, oacc[dt][3] * inv1);
    }
}

// ---------------- layernorm: fp32 in, half out -------------------------------
__global__ __launch_bounds__(256) void ln_kernel(
    const float* __restrict__ x, const float* __restrict__ g,
    const float* __restrict__ bta, __half* __restrict__ y)
{
    const int row = blockIdx.x;
    const float* xr = x + (size_t)row * DD;
    const int tid = threadIdx.x;
    const int lane = tid & 31;
    const int wid = tid >> 5;

    float vals[3];
#pragma unroll
    for (int i = 0; i < 3; ++i) vals[i] = xr[tid + i * 256];

    __shared__ float red[32];

    float sum = vals[0] + vals[1] + vals[2];
#pragma unroll
    for (int off = 16; off >= 1; off >>= 1)
        sum += __shfl_xor_sync(0xffffffffu, sum, off);
    if (lane == 0) red[wid] = sum;
    __syncthreads();
    if (tid < 32) {
        float t = (lane < 8) ? red[lane] : 0.0f;
#pragma unroll
        for (int off = 4; off >= 1; off >>= 1)
            t += __shfl_xor_sync(0xffffffffu, t, off);
        if (lane == 0) red[0] = t * (1.0f / DD);
    }
    __syncthreads();
    const float mu = red[0];
    __syncthreads();

    float vs = 0.0f;
#pragma unroll
    for (int i = 0; i < 3; ++i) {
        const float d = vals[i] - mu;
        vs += d * d;
    }
#pragma unroll
    for (int off = 16; off >= 1; off >>= 1)
        vs += __shfl_xor_sync(0xffffffffu, vs, off);
    if (lane == 0) red[wid] = vs;
    __syncthreads();
    if (tid < 32) {
        float t = (lane < 8) ? red[lane] : 0.0f;
#pragma unroll
        for (int off = 4; off >= 1; off >>= 1)
            t += __shfl_xor_sync(0xffffffffu, t, off);
        if (lane == 0) red[0] = t * (1.0f / DD);
    }
    __syncthreads();
    const float rstd = rsqrtf(red[0] + EPSL);

    __half* yr = y + (size_t)row * DD;
#pragma unroll
    for (int i = 0; i < 3; ++i) {
        const int c = tid + i * 256;
        yr[c] = __float2half_rn((vals[i] - mu) * rstd * g[c] + bta[c]);
    }
}

// ---------------- launch ------------------------------------------------------
extern "C" void kernel_launch(void* const* d_in, const int* in_sizes, int n_in,
                              void* d_out, int out_size)
{
    (void)in_sizes; (void)n_in; (void)out_size;
    const float* Q    = (const float*)d_in[0];
    const float* K    = (const float*)d_in[1];
    const float* V    = (const float*)d_in[2];
    const float* Wq   = (const float*)d_in[3];
    const float* bq   = (const float*)d_in[4];
    const float* Wk   = (const float*)d_in[5];
    const float* bk   = (const float*)d_in[6];
    const float* Wv   = (const float*)d_in[7];
    const float* bv   = (const float*)d_in[8];
    const float* Wo   = (const float*)d_in[9];
    const float* bo   = (const float*)d_in[10];
    const float* ln_g = (const float*)d_in[11];
    const float* ln_b = (const float*)d_in[12];
    const float* W1   = (const float*)d_in[13];
    const float* b1   = (const float*)d_in[14];
    const float* W2   = (const float*)d_in[15];
    const float* b2   = (const float*)d_in[16];
    float* out = (float*)d_out;

    __half* hp = nullptr;
    cudaGetSymbolAddress((void**)&hp, g_half);
    float* gx1 = nullptr;
    cudaGetSymbolAddress((void**)&gx1, g_x1);

    __half* qr   = hp + HO_QR;
    __half* kr   = hp + HO_KR;
    __half* vr   = hp + HO_VR;
    __half* gq   = hp + HO_GQ;
    __half* gk   = hp + HO_GK;
    __half* gv   = hp + HO_GV;
    __half* gctx = hp + HO_CTX;
    __half* gh   = hp + HO_H;
    __half* gff  = hp + HO_FF;
    __half* Wqr  = hp + HO_WQ;
    __half* Wkr  = hp + HO_WK;
    __half* Wvr  = hp + HO_WV;
    __half* Wor  = hp + HO_WO;
    __half* W1r  = hp + HO_W1;
    __half* W2r  = hp + HO_W2;

    cudaFuncSetAttribute(attn_h, cudaFuncAttributeMaxDynamicSharedMemorySize,
                         ATTN_SMEM);
    cudaFuncSetAttribute(hgemm<256, 0, 1>,
                         cudaFuncAttributeMaxDynamicSharedMemorySize, GEMM_SMEM_W);
    cudaFuncSetAttribute(hgemm<256, 2, 1>,
                         cudaFuncAttributeMaxDynamicSharedMemorySize, GEMM_SMEM_W);
    cudaFuncSetAttribute(hgemm<128, 1, 0>,
                         cudaFuncAttributeMaxDynamicSharedMemorySize, GEMM_SMEM_N);
    cudaFuncSetAttribute(hgemm<128, 0, 0>,
                         cudaFuncAttributeMaxDynamicSharedMemorySize, GEMM_SMEM_N);

    const dim3 blk(256);

    // pre-pass: fp32 -> fp16
    f2h<<<SZ_D / 1024, blk>>>(Q, qr, SZ_D / 4);
    f2h<<<SZ_D / 1024, blk>>>(K, kr, SZ_D / 4);
    f2h<<<SZ_D / 1024, blk>>>(V, vr, SZ_D / 4);
    f2h<<<SZ_W / 1024, blk>>>(Wq, Wqr, SZ_W / 4);
    f2h<<<SZ_W / 1024, blk>>>(Wk, Wkr, SZ_W / 4);
    f2h<<<SZ_W / 1024, blk>>>(Wv, Wvr, SZ_W / 4);
    f2h<<<SZ_W / 1024, blk>>>(Wo, Wor, SZ_W / 4);
    f2h<<<SZ_W1 / 1024, blk>>>(W1, W1r, SZ_W1 / 4);
    f2h<<<SZ_W1 / 1024, blk>>>(W2, W2r, SZ_W1 / 4);

    // QKV projections (one wide fused launch; half outputs)
    {
        GSet3 P;
        P.s[0] = { qr, Wqr, bq, nullptr, gq };
        P.s[1] = { kr, Wkr, bk, nullptr, gk };
        P.s[2] = { vr, Wvr, bv, nullptr, gv };
        hgemm<256, 0, 1><<<dim3(DD / 256, MR / 128, 3), blk, GEMM_SMEM_W>>>(
            P, MR, DD, DD);
    }

    // attention
    attn_h<<<dim3(BB * HH, SS / 128), blk, ATTN_SMEM>>>(gq, gk, gv, gctx);

    // output projection + fp32 residual (narrow, 2 CTAs/SM)
    {
        GSet3 P;
        P.s[0] = { gctx, Wor, bo, Q, gx1 };
        P.s[1] = P.s[0]; P.s[2] = P.s[0];
        hgemm<128, 1, 0><<<dim3(DD / 128, MR / 128, 1), dim3(128), GEMM_SMEM_N>>>(
            P, MR, DD, DD);
    }

    // layernorm (fp32 in, half out)
    ln_kernel<<<MR, blk>>>(gx1, ln_g, ln_b, gh);

    // FFN1 (wide, gelu, half out) + FFN2 (narrow, fp32 out)
    {
        GSet3 P;
        P.s[0] = { gh, W1r, b1, nullptr, gff };
        P.s[1] = P.s[0]; P.s[2] = P.s[0];
        hgemm<256, 2, 1><<<dim3(DFF / 256, MR / 128, 1), blk, GEMM_SMEM_W>>>(
            P, MR, DFF, DD);
    }
    {
        GSet3 P;
        P.s[0] = { gff, W2r, b2, nullptr, out };
        P.s[1] = P.s[0]; P.s[2] = P.s[0];
        hgemm<128, 0, 0><<<dim3(DD / 128, MR / 128, 1), dim3(128), GEMM_SMEM_N>>>(
            P, MR, DD, DFF);
    }
}

// round 8
// speedup vs baseline: 5.3374x; 1.0412x over previous
#include <cuda_runtime.h>
#include <cuda_fp16.h>
#include <math.h>
#include <stdint.h>

// Problem constants
#define BB   4
#define SS   2048
#define DD   768
#define HH   12
#define DFF  3072
#define MR   8192          // B*S
#define EPSL 1e-5f

#define SZ_D   (MR * DD)
#define SZ_FF  (MR * DFF)
#define SZ_W   (DD * DD)
#define SZ_W1  (DD * DFF)

// ---------------- scratch ----------------------------------------------------
static __device__ __align__(256) __half g_half[8 * SZ_D + SZ_FF + 4 * SZ_W + 2 * SZ_W1];
static __device__ __align__(256) float g_x1[SZ_D];

#define HO_QR   0
#define HO_KR   (HO_QR + SZ_D)
#define HO_VR   (HO_KR + SZ_D)
#define HO_GQ   (HO_VR + SZ_D)
#define HO_GK   (HO_GQ + SZ_D)
#define HO_GV   (HO_GK + SZ_D)
#define HO_CTX  (HO_GV + SZ_D)
#define HO_H    (HO_CTX + SZ_D)
#define HO_FF   (HO_H + SZ_D)
#define HO_WQ   (HO_FF + SZ_FF)
#define HO_WK   (HO_WQ + SZ_W)
#define HO_WV   (HO_WK + SZ_W)
#define HO_WO   (HO_WV + SZ_W)
#define HO_W1   (HO_WO + SZ_W)
#define HO_W2   (HO_W1 + SZ_W1)

// ---------------- helpers ----------------------------------------------------
__device__ __forceinline__ float gelu_exact(float x) {
    return 0.5f * x * (1.0f + erff(x * 0.70710678118654752f));
}

__device__ __forceinline__ void cpa16(uint32_t s, const void* g) {
    asm volatile("cp.async.cg.shared.global [%0], [%1], 16;" :: "r"(s), "l"(g));
}

__device__ __forceinline__ uint32_t smem_u32(const void* p) {
    uint32_t a;
    asm("{ .reg .u64 t; cvta.to.shared.u64 t, %1; cvt.u32.u64 %0, t; }"
        : "=r"(a) : "l"(p));
    return a;
}

#define LDSM4(r0, r1, r2, r3, addr)                                            \
    asm volatile("ldmatrix.sync.aligned.m8n8.x4.shared.b16 {%0,%1,%2,%3}, [%4];" \
        : "=r"(r0), "=r"(r1), "=r"(r2), "=r"(r3) : "r"(addr))

#define LDSM4T(r0, r1, r2, r3, addr)                                           \
    asm volatile("ldmatrix.sync.aligned.m8n8.x4.trans.shared.b16 {%0,%1,%2,%3}, [%4];" \
        : "=r"(r0), "=r"(r1), "=r"(r2), "=r"(r3) : "r"(addr))

// fp16 warp MMA: D(16x8,f32) += A(16x16,f16) * B(16x8,f16)
__device__ __forceinline__ void mma16(float* c, const uint32_t* a, const uint32_t* b) {
    asm volatile(
        "mma.sync.aligned.m16n8k16.row.col.f32.f16.f16.f32 "
        "{%0,%1,%2,%3}, {%4,%5,%6,%7}, {%8,%9}, {%0,%1,%2,%3};"
        : "+f"(c[0]), "+f"(c[1]), "+f"(c[2]), "+f"(c[3])
        : "r"(a[0]), "r"(a[1]), "r"(a[2]), "r"(a[3]), "r"(b[0]), "r"(b[1]));
}

__device__ __forceinline__ uint32_t pack2h(float lo, float hi) {
    __half2 h = __floats2half2_rn(lo, hi);
    return *(uint32_t*)&h;
}

// ---------------- merged pre-pass: fp32 -> fp16, 9 segments ------------------
// All segment lengths (in float4 units) are multiples of 256, so each block
// maps entirely inside one segment.
struct Seg  { const float* s; __half* d; };
struct Segs { Seg g[9]; int cum[10]; };

__global__ __launch_bounds__(256) void f2h_multi(Segs S)
{
    const int base = blockIdx.x * 256;
    int seg = 0;
#pragma unroll
    for (int j = 1; j < 9; ++j)
        if (base >= S.cum[j]) seg = j;
    const int i = base - S.cum[seg] + threadIdx.x;
    const float4 v = ((const float4*)S.g[seg].s)[i];
    uint2 o;
    o.x = pack2h(v.x, v.y);
    o.y = pack2h(v.z, v.w);
    ((uint2*)S.g[seg].d)[i] = o;
}

// ---------------- fp16 mma GEMM ----------------------------------------------
// C = A[MxK] @ B[KxN] + bias (+epi). A,B half.
// Wide:   CTAM=128, CTAN=256, 256 thr, occ 1.
// Narrow: CTAM=64,  CTAN=128, 128 thr, occ 3 (wave-tail killer).
// EPI: 0 bias, 1 bias+residual(fp32), 2 bias+gelu.  OUTH: 1 -> C half.
struct GSet { const __half* A; const __half* Bm; const float* bias;
              const float* res; void* C; };
struct GSet3 { GSet s[3]; };

#define APADH 24
#define NSTG  4

template <int CTAM, int CTAN, int EPI, int OUTH>
__global__ __launch_bounds__((CTAN == 256) ? 256 : 128, (CTAN == 256) ? 1 : 3)
void hgemm(GSet3 P, int M, int N, int K)
{
    constexpr int T     = (CTAN == 256) ? 256 : 128;   // == CTAM*2
    constexpr int MT    = CTAM / 32;                   // m16 tiles per warp
    constexpr int BPADH = CTAN + 8;
    constexpr int ASTG  = CTAM * APADH;
    constexpr int BSTG  = 16 * BPADH;
    constexpr int NQ    = CTAN / 8;

    extern __shared__ __half hsm[];
    __half* As = hsm;
    __half* Bs = hsm + NSTG * ASTG;

    const GSet gs = P.s[blockIdx.z];
    const __half* __restrict__ A = gs.A;
    const __half* __restrict__ Bm = gs.Bm;
    const float* __restrict__ bias = gs.bias;
    const float* __restrict__ res = gs.res;

    const int tid = threadIdx.x;
    const int wid = tid >> 5;
    const int lane = tid & 31;
    const int wm = wid & 1;
    const int wn = wid >> 1;

    const int bm = blockIdx.y * CTAM;
    const int bn = blockIdx.x * CTAN;

    float acc[MT][8][4];
#pragma unroll
    for (int i = 0; i < MT; ++i)
#pragma unroll
        for (int j = 0; j < 8; ++j)
#pragma unroll
            for (int q = 0; q < 4; ++q) acc[i][j][q] = 0.0f;

    const uint32_t sAb = smem_u32(As);
    const uint32_t sBb = smem_u32(Bs);

    const int KT = K >> 4;

    auto load_stage = [&](int kt) {
        const int st = kt & 3;
        const int k0 = kt << 4;
        const uint32_t aB = sAb + (uint32_t)st * ASTG * 2u;
        const uint32_t bB = sBb + (uint32_t)st * BSTG * 2u;
        {   // A: CTAM*2 chunks == T -> one per thread
            const int m = tid >> 1, hc = (tid & 1) * 8;
            cpa16(aB + (uint32_t)(m * APADH + hc) * 2u,
                  A + (size_t)(bm + m) * K + k0 + hc);
        }
#pragma unroll
        for (int i = 0; i < 2; ++i) {   // B: 2*CTAN chunks
            const int c = tid + i * T;
            const int kr = c / NQ, nq = c % NQ;
            cpa16(bB + (uint32_t)(kr * BPADH + nq * 8) * 2u,
                  Bm + (size_t)(k0 + kr) * N + bn + nq * 8);
        }
        asm volatile("cp.async.commit_group;" ::: "memory");
    };

    load_stage(0); load_stage(1); load_stage(2);

    for (int kt = 0; kt < KT; ++kt) {
        const int rem = KT - 1 - kt;
        if (rem >= 2)      asm volatile("cp.async.wait_group 2;" ::: "memory");
        else if (rem == 1) asm volatile("cp.async.wait_group 1;" ::: "memory");
        else               asm volatile("cp.async.wait_group 0;" ::: "memory");
        __syncthreads();
        if (kt + 3 < KT) load_stage(kt + 3);

        const int st = kt & 3;
        const uint32_t aS = sAb + (uint32_t)st * ASTG * 2u;
        const uint32_t bS = sBb + (uint32_t)st * BSTG * 2u;

        uint32_t au[MT][4], bu[8][2];
#pragma unroll
        for (int mt = 0; mt < MT; ++mt) {
            const int row = wm * (CTAM / 2) + mt * 16 + (lane & 15);
            const int kh = (lane >> 4) * 8;
            LDSM4(au[mt][0], au[mt][1], au[mt][2], au[mt][3],
                  aS + (uint32_t)(row * APADH + kh) * 2u);
        }
#pragma unroll
        for (int ng = 0; ng < 4; ++ng) {
            const int n0 = wn * 64 + ng * 16;
            const uint32_t ad = bS +
                (uint32_t)((lane & 15) * BPADH + n0 + (lane >> 4) * 8) * 2u;
            LDSM4T(bu[2 * ng][0], bu[2 * ng][1],
                   bu[2 * ng + 1][0], bu[2 * ng + 1][1], ad);
        }
#pragma unroll
        for (int mt = 0; mt < MT; ++mt)
#pragma unroll
            for (int nt = 0; nt < 8; ++nt)
                mma16(acc[mt][nt], au[mt], bu[nt]);
    }

    // epilogue
#pragma unroll
    for (int mt = 0; mt < MT; ++mt) {
        const int r0 = bm + wm * (CTAM / 2) + mt * 16 + (lane >> 2);
#pragma unroll
        for (int nt = 0; nt < 8; ++nt) {
            const int col = bn + wn * 64 + nt * 8 + (lane & 3) * 2;
            const float b0 = bias[col], b1 = bias[col + 1];
            float v0 = acc[mt][nt][0] + b0;
            float v1 = acc[mt][nt][1] + b1;
            float v2 = acc[mt][nt][2] + b0;
            float v3 = acc[mt][nt][3] + b1;
            if (EPI == 1) {
                const float2 ra = *(const float2*)&res[(size_t)r0 * N + col];
                const float2 rb = *(const float2*)&res[(size_t)(r0 + 8) * N + col];
                v0 += ra.x; v1 += ra.y; v2 += rb.x; v3 += rb.y;
            }
            if (EPI == 2) {
                v0 = gelu_exact(v0); v1 = gelu_exact(v1);
                v2 = gelu_exact(v2); v3 = gelu_exact(v3);
            }
            if (OUTH) {
                __half* C = (__half*)gs.C;
                *(uint32_t*)&C[(size_t)r0 * N + col] = pack2h(v0, v1);
                *(uint32_t*)&C[(size_t)(r0 + 8) * N + col] = pack2h(v2, v3);
            } else {
                float* C = (float*)gs.C;
                *(float2*)&C[(size_t)r0 * N + col] = make_float2(v0, v1);
                *(float2*)&C[(size_t)(r0 + 8) * N + col] = make_float2(v2, v3);
            }
        }
    }
}

#define GEMM_SMEM_W ((NSTG * (128 * APADH + 16 * (256 + 8))) * 2)
#define GEMM_SMEM_N ((NSTG * (64 * APADH + 16 * (128 + 8))) * 2)

// ---------------- fp16 tensor-core flash attention (unchanged from R7) -------
#define KPADH 72
#define ATTN_SMEM ((128 * KPADH + 2 * 64 * KPADH + 2 * 64 * KPADH) * 2)

__global__ __launch_bounds__(256) void attn_h(
    const __half* __restrict__ q, const __half* __restrict__ k,
    const __half* __restrict__ v, __half* __restrict__ ctx)
{
    extern __shared__ __half asm_[];
    __half* Qs = asm_;                        // [128][72]
    __half* Ks = Qs + 128 * KPADH;            // [2][64][72]
    __half* Vs = Ks + 2 * 64 * KPADH;         // [2][64][72]

    const int bh = blockIdx.x;
    const int qt = blockIdx.y;
    const int b = bh / HH, h = bh % HH;
    const int tid = threadIdx.x;
    const int wid = tid >> 5;
    const int lane = tid & 31;
    const size_t base = (size_t)(b * SS) * DD + h * 64;
    const int q0 = qt * 128;

#pragma unroll
    for (int i = 0; i < 4; ++i) {
        const int idx = tid + i * 256;
        const int r = idx >> 3, hc = idx & 7;
        cpa16(smem_u32(Qs + r * KPADH + hc * 8),
              q + base + (size_t)(q0 + r) * DD + hc * 8);
    }
    asm volatile("cp.async.commit_group; cp.async.wait_group 0;" ::: "memory");
    __syncthreads();

    uint32_t qf[4][4];
    {
        const int row = wid * 16 + (lane & 15);
        const __half2 s8 = __float2half2_rn(0.125f);
#pragma unroll
        for (int dk = 0; dk < 4; ++dk) {
            LDSM4(qf[dk][0], qf[dk][1], qf[dk][2], qf[dk][3],
                  smem_u32(Qs + row * KPADH + dk * 16 + (lane >> 4) * 8));
#pragma unroll
            for (int j = 0; j < 4; ++j) {
                __half2 t = __hmul2(*(__half2*)&qf[dk][j], s8);
                qf[dk][j] = *(uint32_t*)&t;
            }
        }
    }

    float oacc[8][4];
#pragma unroll
    for (int nt = 0; nt < 8; ++nt)
#pragma unroll
        for (int i = 0; i < 4; ++i) oacc[nt][i] = 0.0f;
    float m0 = -INFINITY, m1 = -INFINITY, l0 = 0.0f, l1 = 0.0f;

    auto prefetch = [&](int t) {
        const int buf = t & 1;
#pragma unroll
        for (int i = 0; i < 2; ++i) {
            const int idx = tid + i * 256;
            const int r = idx >> 3, hc = idx & 7;
            const size_t go = base + (size_t)(t * 64 + r) * DD + hc * 8;
            cpa16(smem_u32(Ks + (buf * 64 + r) * KPADH + hc * 8), k + go);
            cpa16(smem_u32(Vs + (buf * 64 + r) * KPADH + hc * 8), v + go);
        }
        asm volatile("cp.async.commit_group;" ::: "memory");
    };

    prefetch(0);

    for (int t = 0; t < SS / 64; ++t) {
        asm volatile("cp.async.wait_group 0;" ::: "memory");
        __syncthreads();
        if (t + 1 < SS / 64) prefetch(t + 1);

        const uint32_t kb = smem_u32(Ks + (t & 1) * 64 * KPADH);
        const uint32_t vb = smem_u32(Vs + (t & 1) * 64 * KPADH);

        float sacc[8][4];
#pragma unroll
        for (int nt = 0; nt < 8; ++nt)
#pragma unroll
            for (int i = 0; i < 4; ++i) sacc[nt][i] = 0.0f;

#pragma unroll
        for (int dk = 0; dk < 4; ++dk) {
            uint32_t ku[8][2];
#pragma unroll
            for (int cg = 0; cg < 4; ++cg) {
                const int row = cg * 16 + (lane & 7) + ((lane >> 4) * 8);
                const int dh = dk * 16 + ((lane >> 3) & 1) * 8;
                LDSM4(ku[2 * cg][0], ku[2 * cg][1],
                      ku[2 * cg + 1][0], ku[2 * cg + 1][1],
                      kb + (uint32_t)(row * KPADH + dh) * 2u);
            }
#pragma unroll
            for (int ct = 0; ct < 8; ++ct) mma16(sacc[ct], qf[dk], ku[ct]);
        }

        float mx0 = -INFINITY, mx1 = -INFINITY;
#pragma unroll
        for (int nt = 0; nt < 8; ++nt) {
            mx0 = fmaxf(mx0, fmaxf(sacc[nt][0], sacc[nt][1]));
            mx1 = fmaxf(mx1, fmaxf(sacc[nt][2], sacc[nt][3]));
        }
        mx0 = fmaxf(mx0, __shfl_xor_sync(0xffffffffu, mx0, 1));
        mx0 = fmaxf(mx0, __shfl_xor_sync(0xffffffffu, mx0, 2));
        mx1 = fmaxf(mx1, __shfl_xor_sync(0xffffffffu, mx1, 1));
        mx1 = fmaxf(mx1, __shfl_xor_sync(0xffffffffu, mx1, 2));

        const float mn0 = fmaxf(m0, mx0), mn1 = fmaxf(m1, mx1);
        const float cor0 = __expf(m0 - mn0), cor1 = __expf(m1 - mn1);
        float rs0 = 0.0f, rs1 = 0.0f;
#pragma unroll
        for (int nt = 0; nt < 8; ++nt) {
            sacc[nt][0] = __expf(sacc[nt][0] - mn0);
            sacc[nt][1] = __expf(sacc[nt][1] - mn0);
            sacc[nt][2] = __expf(sacc[nt][2] - mn1);
            sacc[nt][3] = __expf(sacc[nt][3] - mn1);
            rs0 += sacc[nt][0] + sacc[nt][1];
            rs1 += sacc[nt][2] + sacc[nt][3];
        }
        rs0 += __shfl_xor_sync(0xffffffffu, rs0, 1);
        rs0 += __shfl_xor_sync(0xffffffffu, rs0, 2);
        rs1 += __shfl_xor_sync(0xffffffffu, rs1, 1);
        rs1 += __shfl_xor_sync(0xffffffffu, rs1, 2);

        l0 = l0 * cor0 + rs0;
        l1 = l1 * cor1 + rs1;
        m0 = mn0; m1 = mn1;
#pragma unroll
        for (int nt = 0; nt < 8; ++nt) {
            oacc[nt][0] *= cor0; oacc[nt][1] *= cor0;
            oacc[nt][2] *= cor1; oacc[nt][3] *= cor1;
        }

#pragma unroll
        for (int cc = 0; cc < 4; ++cc) {
            uint32_t af[4];
            af[0] = pack2h(sacc[2 * cc][0], sacc[2 * cc][1]);
            af[1] = pack2h(sacc[2 * cc][2], sacc[2 * cc][3]);
            af[2] = pack2h(sacc[2 * cc + 1][0], sacc[2 * cc + 1][1]);
            af[3] = pack2h(sacc[2 * cc + 1][2], sacc[2 * cc + 1][3]);

            uint32_t vu[8][2];
#pragma unroll
            for (int dg = 0; dg < 4; ++dg) {
                const int row = cc * 16 + (lane & 15);
                const int dh = dg * 16 + (lane >> 4) * 8;
                LDSM4T(vu[2 * dg][0], vu[2 * dg][1],
                       vu[2 * dg + 1][0], vu[2 * dg + 1][1],
                       vb + (uint32_t)(row * KPADH + dh) * 2u);
            }
#pragma unroll
            for (int dt = 0; dt < 8; ++dt) mma16(oacc[dt], af, vu[dt]);
        }
    }

    const float inv0 = 1.0f / l0, inv1 = 1.0f / l1;
    const int row0 = wid * 16 + (lane >> 2);
#pragma unroll
    for (int dt = 0; dt < 8; ++dt) {
        const int col = dt * 8 + (lane & 3) * 2;
        *(uint32_t*)(ctx + base + (size_t)(q0 + row0) * DD + col) =
            pack2h(oacc[dt][0] * inv0, oacc[dt][1] * inv0);
        *(uint32_t*)(ctx + base + (size_t)(q0 + row0 + 8) * DD + col) =
            pack2h(oacc[dt][2] * inv1, oacc[dt][3] * inv1);
    }
}

// ---------------- layernorm: fp32 in, half out -------------------------------
__global__ __launch_bounds__(256) void ln_kernel(
    const float* __restrict__ x, const float* __restrict__ g,
    const float* __restrict__ bta, __half* __restrict__ y)
{
    const int row = blockIdx.x;
    const float* xr = x + (size_t)row * DD;
    const int tid = threadIdx.x;
    const int lane = tid & 31;
    const int wid = tid >> 5;

    float vals[3];
#pragma unroll
    for (int i = 0; i < 3; ++i) vals[i] = xr[tid + i * 256];

    __shared__ float red[32];

    float sum = vals[0] + vals[1] + vals[2];
#pragma unroll
    for (int off = 16; off >= 1; off >>= 1)
        sum += __shfl_xor_sync(0xffffffffu, sum, off);
    if (lane == 0) red[wid] = sum;
    __syncthreads();
    if (tid < 32) {
        float t = (lane < 8) ? red[lane] : 0.0f;
#pragma unroll
        for (int off = 4; off >= 1; off >>= 1)
            t += __shfl_xor_sync(0xffffffffu, t, off);
        if (lane == 0) red[0] = t * (1.0f / DD);
    }
    __syncthreads();
    const float mu = red[0];
    __syncthreads();

    float vs = 0.0f;
#pragma unroll
    for (int i = 0; i < 3; ++i) {
        const float d = vals[i] - mu;
        vs += d * d;
    }
#pragma unroll
    for (int off = 16; off >= 1; off >>= 1)
        vs += __shfl_xor_sync(0xffffffffu, vs, off);
    if (lane == 0) red[wid] = vs;
    __syncthreads();
    if (tid < 32) {
        float t = (lane < 8) ? red[lane] : 0.0f;
#pragma unroll
        for (int off = 4; off >= 1; off >>= 1)
            t += __shfl_xor_sync(0xffffffffu, t, off);
        if (lane == 0) red[0] = t * (1.0f / DD);
    }
    __syncthreads();
    const float rstd = rsqrtf(red[0] + EPSL);

    __half* yr = y + (size_t)row * DD;
#pragma unroll
    for (int i = 0; i < 3; ++i) {
        const int c = tid + i * 256;
        yr[c] = __float2half_rn((vals[i] - mu) * rstd * g[c] + bta[c]);
    }
}

// ---------------- launch ------------------------------------------------------
extern "C" void kernel_launch(void* const* d_in, const int* in_sizes, int n_in,
                              void* d_out, int out_size)
{
    (void)in_sizes; (void)n_in; (void)out_size;
    const float* Q    = (const float*)d_in[0];
    const float* K    = (const float*)d_in[1];
    const float* V    = (const float*)d_in[2];
    const float* Wq   = (const float*)d_in[3];
    const float* bq   = (const float*)d_in[4];
    const float* Wk   = (const float*)d_in[5];
    const float* bk   = (const float*)d_in[6];
    const float* Wv   = (const float*)d_in[7];
    const float* bv   = (const float*)d_in[8];
    const float* Wo   = (const float*)d_in[9];
    const float* bo   = (const float*)d_in[10];
    const float* ln_g = (const float*)d_in[11];
    const float* ln_b = (const float*)d_in[12];
    const float* W1   = (const float*)d_in[13];
    const float* b1   = (const float*)d_in[14];
    const float* W2   = (const float*)d_in[15];
    const float* b2   = (const float*)d_in[16];
    float* out = (float*)d_out;

    __half* hp = nullptr;
    cudaGetSymbolAddress((void**)&hp, g_half);
    float* gx1 = nullptr;
    cudaGetSymbolAddress((void**)&gx1, g_x1);

    __half* qr   = hp + HO_QR;
    __half* kr   = hp + HO_KR;
    __half* vr   = hp + HO_VR;
    __half* gq   = hp + HO_GQ;
    __half* gk   = hp + HO_GK;
    __half* gv   = hp + HO_GV;
    __half* gctx = hp + HO_CTX;
    __half* gh   = hp + HO_H;
    __half* gff  = hp + HO_FF;
    __half* Wqr  = hp + HO_WQ;
    __half* Wkr  = hp + HO_WK;
    __half* Wvr  = hp + HO_WV;
    __half* Wor  = hp + HO_WO;
    __half* W1r  = hp + HO_W1;
    __half* W2r  = hp + HO_W2;

    cudaFuncSetAttribute(attn_h, cudaFuncAttributeMaxDynamicSharedMemorySize,
                         ATTN_SMEM);
    cudaFuncSetAttribute(hgemm<128, 256, 0, 1>,
                         cudaFuncAttributeMaxDynamicSharedMemorySize, GEMM_SMEM_W);
    cudaFuncSetAttribute(hgemm<128, 256, 2, 1>,
                         cudaFuncAttributeMaxDynamicSharedMemorySize, GEMM_SMEM_W);
    cudaFuncSetAttribute(hgemm<64, 128, 1, 0>,
                         cudaFuncAttributeMaxDynamicSharedMemorySize, GEMM_SMEM_N);
    cudaFuncSetAttribute(hgemm<64, 128, 0, 0>,
                         cudaFuncAttributeMaxDynamicSharedMemorySize, GEMM_SMEM_N);

    const dim3 blk(256);

    // merged pre-pass: fp32 -> fp16 (one launch for all 9 segments)
    {
        Segs S;
        const int nD = SZ_D / 4, nW = SZ_W / 4, nW1 = SZ_W1 / 4;
        S.g[0] = { Q,  qr  }; S.g[1] = { K,  kr  }; S.g[2] = { V,  vr  };
        S.g[3] = { Wq, Wqr }; S.g[4] = { Wk, Wkr }; S.g[5] = { Wv, Wvr };
        S.g[6] = { Wo, Wor }; S.g[7] = { W1, W1r }; S.g[8] = { W2, W2r };
        int c = 0;
        const int lens[9] = { nD, nD, nD, nW, nW, nW, nW, nW1, nW1 };
        for (int j = 0; j < 9; ++j) { S.cum[j] = c; c += lens[j]; }
        S.cum[9] = c;
        f2h_multi<<<c / 256, blk>>>(S);
    }

    // QKV projections (one wide fused launch; half outputs)
    {
        GSet3 P;
        P.s[0] = { qr, Wqr, bq, nullptr, gq };
        P.s[1] = { kr, Wkr, bk, nullptr, gk };
        P.s[2] = { vr, Wvr, bv, nullptr, gv };
        hgemm<128, 256, 0, 1><<<dim3(DD / 256, MR / 128, 3), blk, GEMM_SMEM_W>>>(
            P, MR, DD, DD);
    }

    // attention
    attn_h<<<dim3(BB * HH, SS / 128), blk, ATTN_SMEM>>>(gq, gk, gv, gctx);

    // output projection + fp32 residual (narrow 64x128, occ 3)
    {
        GSet3 P;
        P.s[0] = { gctx, Wor, bo, Q, gx1 };
        P.s[1] = P.s[0]; P.s[2] = P.s[0];
        hgemm<64, 128, 1, 0><<<dim3(DD / 128, MR / 64, 1), dim3(128), GEMM_SMEM_N>>>(
            P, MR, DD, DD);
    }

    // layernorm (fp32 in, half out)
    ln_kernel<<<MR, blk>>>(gx1, ln_g, ln_b, gh);

    // FFN1 (wide, gelu, half out) + FFN2 (narrow 64x128, occ 3, fp32 out)
    {
        GSet3 P;
        P.s[0] = { gh, W1r, b1, nullptr, gff };
        P.s[1] = P.s[0]; P.s[2] = P.s[0];
        hgemm<128, 256, 2, 1><<<dim3(DFF / 256, MR / 128, 1), blk, GEMM_SMEM_W>>>(
            P, MR, DFF, DD);
    }
    {
        GSet3 P;
        P.s[0] = { gff, W2r, b2, nullptr, out };
        P.s[1] = P.s[0]; P.s[2] = P.s[0];
        hgemm<64, 128, 0, 0><<<dim3(DD / 128, MR / 64, 1), dim3(128), GEMM_SMEM_N>>>(
            P, MR, DD, DFF);
    }
}

// round 9
// speedup vs baseline: 5.3383x; 1.0002x over previous
#include <cuda_runtime.h>
#include <cuda_fp16.h>
#include <math.h>
#include <stdint.h>

// Problem constants
#define BB   4
#define SS   2048
#define DD   768
#define HH   12
#define DFF  3072
#define MR   8192          // B*S
#define EPSL 1e-5f

#define SZ_D   (MR * DD)
#define SZ_FF  (MR * DFF)
#define SZ_W   (DD * DD)
#define SZ_W1  (DD * DFF)

// ---------------- scratch ----------------------------------------------------
static __device__ __align__(256) __half g_half[8 * SZ_D + SZ_FF + 4 * SZ_W + 2 * SZ_W1];
static __device__ __align__(256) float g_x1[SZ_D];

#define HO_QR   0
#define HO_KR   (HO_QR + SZ_D)
#define HO_VR   (HO_KR + SZ_D)
#define HO_GQ   (HO_VR + SZ_D)
#define HO_GK   (HO_GQ + SZ_D)
#define HO_GV   (HO_GK + SZ_D)
#define HO_CTX  (HO_GV + SZ_D)
#define HO_H    (HO_CTX + SZ_D)
#define HO_FF   (HO_H + SZ_D)
#define HO_WQ   (HO_FF + SZ_FF)
#define HO_WK   (HO_WQ + SZ_W)
#define HO_WV   (HO_WK + SZ_W)
#define HO_WO   (HO_WV + SZ_W)
#define HO_W1   (HO_WO + SZ_W)
#define HO_W2   (HO_W1 + SZ_W1)

// ---------------- helpers ----------------------------------------------------
__device__ __forceinline__ float gelu_exact(float x) {
    return 0.5f * x * (1.0f + erff(x * 0.70710678118654752f));
}

__device__ __forceinline__ void cpa16(uint32_t s, const void* g) {
    asm volatile("cp.async.cg.shared.global [%0], [%1], 16;" :: "r"(s), "l"(g));
}

__device__ __forceinline__ uint32_t smem_u32(const void* p) {
    uint32_t a;
    asm("{ .reg .u64 t; cvta.to.shared.u64 t, %1; cvt.u32.u64 %0, t; }"
        : "=r"(a) : "l"(p));
    return a;
}

#define LDSM4(r0, r1, r2, r3, addr)                                            \
    asm volatile("ldmatrix.sync.aligned.m8n8.x4.shared.b16 {%0,%1,%2,%3}, [%4];" \
        : "=r"(r0), "=r"(r1), "=r"(r2), "=r"(r3) : "r"(addr))

#define LDSM4T(r0, r1, r2, r3, addr)                                           \
    asm volatile("ldmatrix.sync.aligned.m8n8.x4.trans.shared.b16 {%0,%1,%2,%3}, [%4];" \
        : "=r"(r0), "=r"(r1), "=r"(r2), "=r"(r3) : "r"(addr))

// fp16 warp MMA: D(16x8,f32) += A(16x16,f16) * B(16x8,f16)
__device__ __forceinline__ void mma16(float* c, const uint32_t* a, const uint32_t* b) {
    asm volatile(
        "mma.sync.aligned.m16n8k16.row.col.f32.f16.f16.f32 "
        "{%0,%1,%2,%3}, {%4,%5,%6,%7}, {%8,%9}, {%0,%1,%2,%3};"
        : "+f"(c[0]), "+f"(c[1]), "+f"(c[2]), "+f"(c[3])
        : "r"(a[0]), "r"(a[1]), "r"(a[2]), "r"(a[3]), "r"(b[0]), "r"(b[1]));
}

__device__ __forceinline__ uint32_t pack2h(float lo, float hi) {
    __half2 h = __floats2half2_rn(lo, hi);
    return *(uint32_t*)&h;
}

// ---------------- merged pre-pass: fp32 -> fp16, 9 segments ------------------
// All segment lengths (in float4 units) are multiples of 256, so each block
// maps entirely inside one segment.
struct Seg  { const float* s; __half* d; };
struct Segs { Seg g[9]; int cum[10]; };

__global__ __launch_bounds__(256) void f2h_multi(Segs S)
{
    const int base = blockIdx.x * 256;
    int seg = 0;
#pragma unroll
    for (int j = 1; j < 9; ++j)
        if (base >= S.cum[j]) seg = j;
    const int i = base - S.cum[seg] + threadIdx.x;
    const float4 v = ((const float4*)S.g[seg].s)[i];
    uint2 o;
    o.x = pack2h(v.x, v.y);
    o.y = pack2h(v.z, v.w);
    ((uint2*)S.g[seg].d)[i] = o;
}

// ---------------- fp16 mma GEMM ----------------------------------------------
// C = A[MxK] @ B[KxN] + bias (+epi). A,B half.
// Wide:   CTAM=128, CTAN=256, 256 thr, occ 1.
// Narrow: CTAM=64,  CTAN=128, 128 thr, occ 3 (wave-tail killer).
// EPI: 0 bias, 1 bias+residual(fp32), 2 bias+gelu.  OUTH: 1 -> C half.
struct GSet { const __half* A; const __half* Bm; const float* bias;
              const float* res; void* C; };
struct GSet3 { GSet s[3]; };

#define APADH 24
#define NSTG  4

template <int CTAM, int CTAN, int EPI, int OUTH>
__global__ __launch_bounds__((CTAN == 256) ? 256 : 128, (CTAN == 256) ? 1 : 3)
void hgemm(GSet3 P, int M, int N, int K)
{
    constexpr int T     = (CTAN == 256) ? 256 : 128;   // == CTAM*2
    constexpr int MT    = CTAM / 32;                   // m16 tiles per warp
    constexpr int BPADH = CTAN + 8;
    constexpr int ASTG  = CTAM * APADH;
    constexpr int BSTG  = 16 * BPADH;
    constexpr int NQ    = CTAN / 8;

    extern __shared__ __half hsm[];
    __half* As = hsm;
    __half* Bs = hsm + NSTG * ASTG;

    const GSet gs = P.s[blockIdx.z];
    const __half* __restrict__ A = gs.A;
    const __half* __restrict__ Bm = gs.Bm;
    const float* __restrict__ bias = gs.bias;
    const float* __restrict__ res = gs.res;

    const int tid = threadIdx.x;
    const int wid = tid >> 5;
    const int lane = tid & 31;
    const int wm = wid & 1;
    const int wn = wid >> 1;

    const int bm = blockIdx.y * CTAM;
    const int bn = blockIdx.x * CTAN;

    float acc[MT][8][4];
#pragma unroll
    for (int i = 0; i < MT; ++i)
#pragma unroll
        for (int j = 0; j < 8; ++j)
#pragma unroll
            for (int q = 0; q < 4; ++q) acc[i][j][q] = 0.0f;

    const uint32_t sAb = smem_u32(As);
    const uint32_t sBb = smem_u32(Bs);

    const int KT = K >> 4;

    auto load_stage = [&](int kt) {
        const int st = kt & 3;
        const int k0 = kt << 4;
        const uint32_t aB = sAb + (uint32_t)st * ASTG * 2u;
        const uint32_t bB = sBb + (uint32_t)st * BSTG * 2u;
        {   // A: CTAM*2 chunks == T -> one per thread
            const int m = tid >> 1, hc = (tid & 1) * 8;
            cpa16(aB + (uint32_t)(m * APADH + hc) * 2u,
                  A + (size_t)(bm + m) * K + k0 + hc);
        }
#pragma unroll
        for (int i = 0; i < 2; ++i) {   // B: 2*CTAN chunks
            const int c = tid + i * T;
            const int kr = c / NQ, nq = c % NQ;
            cpa16(bB + (uint32_t)(kr * BPADH + nq * 8) * 2u,
                  Bm + (size_t)(k0 + kr) * N + bn + nq * 8);
        }
        asm volatile("cp.async.commit_group;" ::: "memory");
    };

    load_stage(0); load_stage(1); load_stage(2);

    for (int kt = 0; kt < KT; ++kt) {
        const int rem = KT - 1 - kt;
        if (rem >= 2)      asm volatile("cp.async.wait_group 2;" ::: "memory");
        else if (rem == 1) asm volatile("cp.async.wait_group 1;" ::: "memory");
        else               asm volatile("cp.async.wait_group 0;" ::: "memory");
        __syncthreads();
        if (kt + 3 < KT) load_stage(kt + 3);

        const int st = kt & 3;
        const uint32_t aS = sAb + (uint32_t)st * ASTG * 2u;
        const uint32_t bS = sBb + (uint32_t)st * BSTG * 2u;

        uint32_t au[MT][4], bu[8][2];
#pragma unroll
        for (int mt = 0; mt < MT; ++mt) {
            const int row = wm * (CTAM / 2) + mt * 16 + (lane & 15);
            const int kh = (lane >> 4) * 8;
            LDSM4(au[mt][0], au[mt][1], au[mt][2], au[mt][3],
                  aS + (uint32_t)(row * APADH + kh) * 2u);
        }
#pragma unroll
        for (int ng = 0; ng < 4; ++ng) {
            const int n0 = wn * 64 + ng * 16;
            const uint32_t ad = bS +
                (uint32_t)((lane & 15) * BPADH + n0 + (lane >> 4) * 8) * 2u;
            LDSM4T(bu[2 * ng][0], bu[2 * ng][1],
                   bu[2 * ng + 1][0], bu[2 * ng + 1][1], ad);
        }
#pragma unroll
        for (int mt = 0; mt < MT; ++mt)
#pragma unroll
            for (int nt = 0; nt < 8; ++nt)
                mma16(acc[mt][nt], au[mt], bu[nt]);
    }

    // epilogue
#pragma unroll
    for (int mt = 0; mt < MT; ++mt) {
        const int r0 = bm + wm * (CTAM / 2) + mt * 16 + (lane >> 2);
#pragma unroll
        for (int nt = 0; nt < 8; ++nt) {
            const int col = bn + wn * 64 + nt * 8 + (lane & 3) * 2;
            const float b0 = bias[col], b1 = bias[col + 1];
            float v0 = acc[mt][nt][0] + b0;
            float v1 = acc[mt][nt][1] + b1;
            float v2 = acc[mt][nt][2] + b0;
            float v3 = acc[mt][nt][3] + b1;
            if (EPI == 1) {
                const float2 ra = *(const float2*)&res[(size_t)r0 * N + col];
                const float2 rb = *(const float2*)&res[(size_t)(r0 + 8) * N + col];
                v0 += ra.x; v1 += ra.y; v2 += rb.x; v3 += rb.y;
            }
            if (EPI == 2) {
                v0 = gelu_exact(v0); v1 = gelu_exact(v1);
                v2 = gelu_exact(v2); v3 = gelu_exact(v3);
            }
            if (OUTH) {
                __half* C = (__half*)gs.C;
                *(uint32_t*)&C[(size_t)r0 * N + col] = pack2h(v0, v1);
                *(uint32_t*)&C[(size_t)(r0 + 8) * N + col] = pack2h(v2, v3);
            } else {
                float* C = (float*)gs.C;
                *(float2*)&C[(size_t)r0 * N + col] = make_float2(v0, v1);
                *(float2*)&C[(size_t)(r0 + 8) * N + col] = make_float2(v2, v3);
            }
        }
    }
}

#define GEMM_SMEM_W ((NSTG * (128 * APADH + 16 * (256 + 8))) * 2)
#define GEMM_SMEM_N ((NSTG * (64 * APADH + 16 * (128 + 8))) * 2)

// ---------------- fp16 tensor-core flash attention (unchanged from R7) -------
#define KPADH 72
#define ATTN_SMEM ((128 * KPADH + 2 * 64 * KPADH + 2 * 64 * KPADH) * 2)

__global__ __launch_bounds__(256) void attn_h(
    const __half* __restrict__ q, const __half* __restrict__ k,
    const __half* __restrict__ v, __half* __restrict__ ctx)
{
    extern __shared__ __half asm_[];
    __half* Qs = asm_;                        // [128][72]
    __half* Ks = Qs + 128 * KPADH;            // [2][64][72]
    __half* Vs = Ks + 2 * 64 * KPADH;         // [2][64][72]

    const int bh = blockIdx.x;
    const int qt = blockIdx.y;
    const int b = bh / HH, h = bh % HH;
    const int tid = threadIdx.x;
    const int wid = tid >> 5;
    const int lane = tid & 31;
    const size_t base = (size_t)(b * SS) * DD + h * 64;
    const int q0 = qt * 128;

#pragma unroll
    for (int i = 0; i < 4; ++i) {
        const int idx = tid + i * 256;
        const int r = idx >> 3, hc = idx & 7;
        cpa16(smem_u32(Qs + r * KPADH + hc * 8),
              q + base + (size_t)(q0 + r) * DD + hc * 8);
    }
    asm volatile("cp.async.commit_group; cp.async.wait_group 0;" ::: "memory");
    __syncthreads();

    uint32_t qf[4][4];
    {
        const int row = wid * 16 + (lane & 15);
        const __half2 s8 = __float2half2_rn(0.125f);
#pragma unroll
        for (int dk = 0; dk < 4; ++dk) {
            LDSM4(qf[dk][0], qf[dk][1], qf[dk][2], qf[dk][3],
                  smem_u32(Qs + row * KPADH + dk * 16 + (lane >> 4) * 8));
#pragma unroll
            for (int j = 0; j < 4; ++j) {
                __half2 t = __hmul2(*(__half2*)&qf[dk][j], s8);
                qf[dk][j] = *(uint32_t*)&t;
            }
        }
    }

    float oacc[8][4];
#pragma unroll
    for (int nt = 0; nt < 8; ++nt)
#pragma unroll
        for (int i = 0; i < 4; ++i) oacc[nt][i] = 0.0f;
    float m0 = -INFINITY, m1 = -INFINITY, l0 = 0.0f, l1 = 0.0f;

    auto prefetch = [&](int t) {
        const int buf = t & 1;
#pragma unroll
        for (int i = 0; i < 2; ++i) {
            const int idx = tid + i * 256;
            const int r = idx >> 3, hc = idx & 7;
            const size_t go = base + (size_t)(t * 64 + r) * DD + hc * 8;
            cpa16(smem_u32(Ks + (buf * 64 + r) * KPADH + hc * 8), k + go);
            cpa16(smem_u32(Vs + (buf * 64 + r) * KPADH + hc * 8), v + go);
        }
        asm volatile("cp.async.commit_group;" ::: "memory");
    };

    prefetch(0);

    for (int t = 0; t < SS / 64; ++t) {
        asm volatile("cp.async.wait_group 0;" ::: "memory");
        __syncthreads();
        if (t + 1 < SS / 64) prefetch(t + 1);

        const uint32_t kb = smem_u32(Ks + (t & 1) * 64 * KPADH);
        const uint32_t vb = smem_u32(Vs + (t & 1) * 64 * KPADH);

        float sacc[8][4];
#pragma unroll
        for (int nt = 0; nt < 8; ++nt)
#pragma unroll
            for (int i = 0; i < 4; ++i) sacc[nt][i] = 0.0f;

#pragma unroll
        for (int dk = 0; dk < 4; ++dk) {
            uint32_t ku[8][2];
#pragma unroll
            for (int cg = 0; cg < 4; ++cg) {
                const int row = cg * 16 + (lane & 7) + ((lane >> 4) * 8);
                const int dh = dk * 16 + ((lane >> 3) & 1) * 8;
                LDSM4(ku[2 * cg][0], ku[2 * cg][1],
                      ku[2 * cg + 1][0], ku[2 * cg + 1][1],
                      kb + (uint32_t)(row * KPADH + dh) * 2u);
            }
#pragma unroll
            for (int ct = 0; ct < 8; ++ct) mma16(sacc[ct], qf[dk], ku[ct]);
        }

        float mx0 = -INFINITY, mx1 = -INFINITY;
#pragma unroll
        for (int nt = 0; nt < 8; ++nt) {
            mx0 = fmaxf(mx0, fmaxf(sacc[nt][0], sacc[nt][1]));
            mx1 = fmaxf(mx1, fmaxf(sacc[nt][2], sacc[nt][3]));
        }
        mx0 = fmaxf(mx0, __shfl_xor_sync(0xffffffffu, mx0, 1));
        mx0 = fmaxf(mx0, __shfl_xor_sync(0xffffffffu, mx0, 2));
        mx1 = fmaxf(mx1, __shfl_xor_sync(0xffffffffu, mx1, 1));
        mx1 = fmaxf(mx1, __shfl_xor_sync(0xffffffffu, mx1, 2));

        const float mn0 = fmaxf(m0, mx0), mn1 = fmaxf(m1, mx1);
        const float cor0 = __expf(m0 - mn0), cor1 = __expf(m1 - mn1);
        float rs0 = 0.0f, rs1 = 0.0f;
#pragma unroll
        for (int nt = 0; nt < 8; ++nt) {
            sacc[nt][0] = __expf(sacc[nt][0] - mn0);
            sacc[nt][1] = __expf(sacc[nt][1] - mn0);
            sacc[nt][2] = __expf(sacc[nt][2] - mn1);
            sacc[nt][3] = __expf(sacc[nt][3] - mn1);
            rs0 += sacc[nt][0] + sacc[nt][1];
            rs1 += sacc[nt][2] + sacc[nt][3];
        }
        rs0 += __shfl_xor_sync(0xffffffffu, rs0, 1);
        rs0 += __shfl_xor_sync(0xffffffffu, rs0, 2);
        rs1 += __shfl_xor_sync(0xffffffffu, rs1, 1);
        rs1 += __shfl_xor_sync(0xffffffffu, rs1, 2);

        l0 = l0 * cor0 + rs0;
        l1 = l1 * cor1 + rs1;
        m0 = mn0; m1 = mn1;
#pragma unroll
        for (int nt = 0; nt < 8; ++nt) {
            oacc[nt][0] *= cor0; oacc[nt][1] *= cor0;
            oacc[nt][2] *= cor1; oacc[nt][3] *= cor1;
        }

#pragma unroll
        for (int cc = 0; cc < 4; ++cc) {
            uint32_t af[4];
            af[0] = pack2h(sacc[2 * cc][0], sacc[2 * cc][1]);
            af[1] = pack2h(sacc[2 * cc][2], sacc[2 * cc][3]);
            af[2] = pack2h(sacc[2 * cc + 1][0], sacc[2 * cc + 1][1]);
            af[3] = pack2h(sacc[2 * cc + 1][2], sacc[2 * cc + 1][3]);

            uint32_t vu[8][2];
#pragma unroll
            for (int dg = 0; dg < 4; ++dg) {
                const int row = cc * 16 + (lane & 15);
                const int dh = dg * 16 + (lane >> 4) * 8;
                LDSM4T(vu[2 * dg][0], vu[2 * dg][1],
                       vu[2 * dg + 1][0], vu[2 * dg + 1][1],
                       vb + (uint32_t)(row * KPADH + dh) * 2u);
            }
#pragma unroll
            for (int dt = 0; dt < 8; ++dt) mma16(oacc[dt], af, vu[dt]);
        }
    }

    const float inv0 = 1.0f / l0, inv1 = 1.0f / l1;
    const int row0 = wid * 16 + (lane >> 2);
#pragma unroll
    for (int dt = 0; dt < 8; ++dt) {
        const int col = dt * 8 + (lane & 3) * 2;
        *(uint32_t*)(ctx + base + (size_t)(q0 + row0) * DD + col) =
            pack2h(oacc[dt][0] * inv0, oacc[dt][1] * inv0);
        *(uint32_t*)(ctx + base + (size_t)(q0 + row0 + 8) * DD + col) =
            pack2h(oacc[dt][2] * inv1, oacc[dt][3] * inv1);
    }
}

// ---------------- layernorm: fp32 in, half out -------------------------------
__global__ __launch_bounds__(256) void ln_kernel(
    const float* __restrict__ x, const float* __restrict__ g,
    const float* __restrict__ bta, __half* __restrict__ y)
{
    const int row = blockIdx.x;
    const float* xr = x + (size_t)row * DD;
    const int tid = threadIdx.x;
    const int lane = tid & 31;
    const int wid = tid >> 5;

    float vals[3];
#pragma unroll
    for (int i = 0; i < 3; ++i) vals[i] = xr[tid + i * 256];

    __shared__ float red[32];

    float sum = vals[0] + vals[1] + vals[2];
#pragma unroll
    for (int off = 16; off >= 1; off >>= 1)
        sum += __shfl_xor_sync(0xffffffffu, sum, off);
    if (lane == 0) red[wid] = sum;
    __syncthreads();
    if (tid < 32) {
        float t = (lane < 8) ? red[lane] : 0.0f;
#pragma unroll
        for (int off = 4; off >= 1; off >>= 1)
            t += __shfl_xor_sync(0xffffffffu, t, off);
        if (lane == 0) red[0] = t * (1.0f / DD);
    }
    __syncthreads();
    const float mu = red[0];
    __syncthreads();

    float vs = 0.0f;
#pragma unroll
    for (int i = 0; i < 3; ++i) {
        const float d = vals[i] - mu;
        vs += d * d;
    }
#pragma unroll
    for (int off = 16; off >= 1; off >>= 1)
        vs += __shfl_xor_sync(0xffffffffu, vs, off);
    if (lane == 0) red[wid] = vs;
    __syncthreads();
    if (tid < 32) {
        float t = (lane < 8) ? red[lane] : 0.0f;
#pragma unroll
        for (int off = 4; off >= 1; off >>= 1)
            t += __shfl_xor_sync(0xffffffffu, t, off);
        if (lane == 0) red[0] = t * (1.0f / DD);
    }
    __syncthreads();
    const float rstd = rsqrtf(red[0] + EPSL);

    __half* yr = y + (size_t)row * DD;
#pragma unroll
    for (int i = 0; i < 3; ++i) {
        const int c = tid + i * 256;
        yr[c] = __float2half_rn((vals[i] - mu) * rstd * g[c] + bta[c]);
    }
}

// ---------------- launch ------------------------------------------------------
extern "C" void kernel_launch(void* const* d_in, const int* in_sizes, int n_in,
                              void* d_out, int out_size)
{
    (void)in_sizes; (void)n_in; (void)out_size;
    const float* Q    = (const float*)d_in[0];
    const float* K    = (const float*)d_in[1];
    const float* V    = (const float*)d_in[2];
    const float* Wq   = (const float*)d_in[3];
    const float* bq   = (const float*)d_in[4];
    const float* Wk   = (const float*)d_in[5];
    const float* bk   = (const float*)d_in[6];
    const float* Wv   = (const float*)d_in[7];
    const float* bv   = (const float*)d_in[8];
    const float* Wo   = (const float*)d_in[9];
    const float* bo   = (const float*)d_in[10];
    const float* ln_g = (const float*)d_in[11];
    const float* ln_b = (const float*)d_in[12];
    const float* W1   = (const float*)d_in[13];
    const float* b1   = (const float*)d_in[14];
    const float* W2   = (const float*)d_in[15];
    const float* b2   = (const float*)d_in[16];
    float* out = (float*)d_out;

    __half* hp = nullptr;
    cudaGetSymbolAddress((void**)&hp, g_half);
    float* gx1 = nullptr;
    cudaGetSymbolAddress((void**)&gx1, g_x1);

    __half* qr   = hp + HO_QR;
    __half* kr   = hp + HO_KR;
    __half* vr   = hp + HO_VR;
    __half* gq   = hp + HO_GQ;
    __half* gk   = hp + HO_GK;
    __half* gv   = hp + HO_GV;
    __half* gctx = hp + HO_CTX;
    __half* gh   = hp + HO_H;
    __half* gff  = hp + HO_FF;
    __half* Wqr  = hp + HO_WQ;
    __half* Wkr  = hp + HO_WK;
    __half* Wvr  = hp + HO_WV;
    __half* Wor  = hp + HO_WO;
    __half* W1r  = hp + HO_W1;
    __half* W2r  = hp + HO_W2;

    cudaFuncSetAttribute(attn_h, cudaFuncAttributeMaxDynamicSharedMemorySize,
                         ATTN_SMEM);
    cudaFuncSetAttribute(hgemm<128, 256, 0, 1>,
                         cudaFuncAttributeMaxDynamicSharedMemorySize, GEMM_SMEM_W);
    cudaFuncSetAttribute(hgemm<128, 256, 2, 1>,
                         cudaFuncAttributeMaxDynamicSharedMemorySize, GEMM_SMEM_W);
    cudaFuncSetAttribute(hgemm<64, 128, 1, 0>,
                         cudaFuncAttributeMaxDynamicSharedMemorySize, GEMM_SMEM_N);
    cudaFuncSetAttribute(hgemm<64, 128, 0, 0>,
                         cudaFuncAttributeMaxDynamicSharedMemorySize, GEMM_SMEM_N);

    const dim3 blk(256);

    // merged pre-pass: fp32 -> fp16 (one launch for all 9 segments)
    {
        Segs S;
        const int nD = SZ_D / 4, nW = SZ_W / 4, nW1 = SZ_W1 / 4;
        S.g[0] = { Q,  qr  }; S.g[1] = { K,  kr  }; S.g[2] = { V,  vr  };
        S.g[3] = { Wq, Wqr }; S.g[4] = { Wk, Wkr }; S.g[5] = { Wv, Wvr };
        S.g[6] = { Wo, Wor }; S.g[7] = { W1, W1r }; S.g[8] = { W2, W2r };
        int c = 0;
        const int lens[9] = { nD, nD, nD, nW, nW, nW, nW, nW1, nW1 };
        for (int j = 0; j < 9; ++j) { S.cum[j] = c; c += lens[j]; }
        S.cum[9] = c;
        f2h_multi<<<c / 256, blk>>>(S);
    }

    // QKV projections (one wide fused launch; half outputs)
    {
        GSet3 P;
        P.s[0] = { qr, Wqr, bq, nullptr, gq };
        P.s[1] = { kr, Wkr, bk, nullptr, gk };
        P.s[2] = { vr, Wvr, bv, nullptr, gv };
        hgemm<128, 256, 0, 1><<<dim3(DD / 256, MR / 128, 3), blk, GEMM_SMEM_W>>>(
            P, MR, DD, DD);
    }

    // attention
    attn_h<<<dim3(BB * HH, SS / 128), blk, ATTN_SMEM>>>(gq, gk, gv, gctx);

    // output projection + fp32 residual (narrow 64x128, occ 3)
    {
        GSet3 P;
        P.s[0] = { gctx, Wor, bo, Q, gx1 };
        P.s[1] = P.s[0]; P.s[2] = P.s[0];
        hgemm<64, 128, 1, 0><<<dim3(DD / 128, MR / 64, 1), dim3(128), GEMM_SMEM_N>>>(
            P, MR, DD, DD);
    }

    // layernorm (fp32 in, half out)
    ln_kernel<<<MR, blk>>>(gx1, ln_g, ln_b, gh);

    // FFN1 (wide, gelu, half out) + FFN2 (narrow 64x128, occ 3, fp32 out)
    {
        GSet3 P;
        P.s[0] = { gh, W1r, b1, nullptr, gff };
        P.s[1] = P.s[0]; P.s[2] = P.s[0];
        hgemm<128, 256, 2, 1><<<dim3(DFF / 256, MR / 128, 1), blk, GEMM_SMEM_W>>>(
            P, MR, DFF, DD);
    }
    {
        GSet3 P;
        P.s[0] = { gff, W2r, b2, nullptr, out };
        P.s[1] = P.s[0]; P.s[2] = P.s[0];
        hgemm<64, 128, 0, 0><<<dim3(DD / 128, MR / 64, 1), dim3(128), GEMM_SMEM_N>>>(
            P, MR, DD, DFF);
    }
}